// round 6
// baseline (speedup 1.0000x reference)
#include <cuda_runtime.h>
#include <stdint.h>
#include <math.h>

#define N_   2048
#define B_   2
#define C_   512
#define BN   (B_*N_)
#define EPSF 1e-8f
#define BIGF 1e9f

// ---------------- device scratch (no allocation allowed) ----------------
__device__ float  g_nrm1[BN], g_nrm2[BN];
__device__ float  g_f1n[BN*C_], g_f2n[BN*C_];
__device__ float4 g_xy1p[BN], g_xy2p[BN], g_xy11p[BN];   // (x, y, rb, 0)
__device__ int    g_nbA[BN*12], g_nbB[BN*12];
__device__ int    g_nn1i[BN*32];     // unmasked top-32 self-KNN of xy1: indices
__device__ float  g_nn1d[BN*32];     // and squared distances
__device__ int    g_cand[BN*4];
__device__ float  g_Kc[BN*4];
__device__ int    g_sord[BN];
__device__ int    g_ccnt[B_*N_], g_coff[B_*N_];
__device__ int    g_tlist[B_*N_*4];
__device__ int    g_idx0[BN], g_idxA[BN], g_maskA[BN], g_idx1[BN], g_mask[BN];
__device__ float  g_flow[BN*2], g_fgri[BN*2];
__device__ float  g_rowD[BN*2];
__device__ int    g_rowIdx[BN*2];
__device__ int    g_colArg[BN];
__device__ int    g_cntA[B_], g_cntM[B_];
__device__ float  g_par[2];   // [0]=eps, [1]=power

__global__ void k_params(const float* gam, const float* eps){
  float e = __fadd_rn(expf(eps[0]), 0.03f);
  float g = expf(gam[0]);
  g_par[0] = e;
  g_par[1] = __fdiv_rn(g, __fadd_rn(g, e));
}

__global__ void k_norms(const float* __restrict__ f1, const float* __restrict__ f2){
  int w = (blockIdx.x*blockDim.x + threadIdx.x) >> 5;
  int lane = threadIdx.x & 31;
  if (w >= 2*BN) return;
  const float* f = (w < BN) ? (f1 + (size_t)w*C_) : (f2 + (size_t)(w-BN)*C_);
  float s = 0.f;
  for (int c = lane; c < C_; c += 32) s = __fmaf_rn(f[c], f[c], s);
  #pragma unroll
  for (int off=16; off; off>>=1) s = __fadd_rn(s, __shfl_xor_sync(0xffffffffu, s, off));
  if (lane == 0){
    float n = __fadd_rn(sqrtf(s), EPSF);
    if (w < BN) g_nrm1[w] = n; else g_nrm2[w-BN] = n;
  }
}

__global__ void k_normalize(const float* __restrict__ f1, const float* __restrict__ f2){
  int e = blockIdx.x*blockDim.x + threadIdx.x;
  const int tot = BN*C_;
  if (e < tot){
    g_f1n[e] = __fdiv_rn(f1[e], g_nrm1[e / C_]);
  } else if (e < 2*tot){
    int e2 = e - tot;
    g_f2n[e2] = __fdiv_rn(f2[e2], g_nrm2[e2 / C_]);
  }
}

__global__ void k_prep(const float* __restrict__ xy, float4* __restrict__ dst, int addflow){
  int p = blockIdx.x*blockDim.x + threadIdx.x;
  if (p >= BN) return;
  float x = xy[p*2], y = xy[p*2+1];
  if (addflow){ x = __fadd_rn(x, g_fgri[p*2]); y = __fadd_rn(y, g_fgri[p*2+1]); }
  dst[p] = make_float4(x, y, __fmaf_rn(y, y, __fmul_rn(x, x)), 0.f);
}

// ---------------- warp-per-row brute force top-K with fp32 screening ----------------
template<int K, bool MASKC, bool EYE, bool SQRT>
__device__ __forceinline__ void warp_topk(
    const float4* __restrict__ Q, const float4* __restrict__ R,
    const int* __restrict__ maskc, int row, unsigned long long (&out)[K])
{
  int lane = threadIdx.x & 31;
  int b = row / N_, i = row - b*N_;
  float4 q = __ldg(&Q[row]);
  const float4* Rb = R + (size_t)b*N_;
  const int* M = MASKC ? (maskc + b*N_) : nullptr;

  unsigned long long best[K];
  #pragma unroll
  for (int s=0; s<K; s++) best[s] = 0x7F800000FFFFFFFFull;  // d=+inf
  float dlast = __uint_as_float(0x7F800000u);
  float U     = __uint_as_float(0x7FC00000u);               // NaN -> never skip initially

  #pragma unroll 4
  for (int t=0; t<N_/32; t++){
    int j = lane + 32*t;
    float4 r = __ldg(&Rb[j]);
    float dt = __fmaf_rn(q.y, r.y, __fmul_rn(q.x, r.x));
    float d  = fmaxf(__fsub_rn(__fadd_rn(q.z, r.z), __fmul_rn(2.0f, dt)), 0.0f);
    if (MASKC){ if (!__ldg(&M[j])) d = BIGF; }
    if (EYE){ if (j == i) d = __fadd_rn(d, BIGF); }
    bool try_ins;
    if (SQRT){
      float d2pe = __fadd_rn(d, EPSF);
      try_ins = !(d2pe > U);
      if (try_ins) d = sqrtf(d2pe);
    } else {
      try_ins = (d <= dlast);
    }
    if (try_ins){
      unsigned long long key = ((unsigned long long)__float_as_uint(d) << 32) | (unsigned)j;
      if (key < best[K-1]){
        best[K-1] = key;
        #pragma unroll
        for (int s=K-1; s>0; s--){
          if (best[s] < best[s-1]){
            unsigned long long tmp = best[s-1]; best[s-1] = best[s]; best[s] = tmp;
          } else break;
        }
        unsigned hb = (unsigned)(best[K-1] >> 32);
        if (SQRT){
          float up = __uint_as_float(hb + 1);
          U = __fmul_ru(up, up);
        } else {
          dlast = __uint_as_float(hb);
        }
      }
    }
  }
  #pragma unroll
  for (int s=0; s<K; s++){
    unsigned long long c = best[0];
    unsigned long long m = c;
    #pragma unroll
    for (int off=16; off; off>>=1){
      unsigned long long o = __shfl_xor_sync(0xffffffffu, m, off);
      m = (o < m) ? o : m;
    }
    if (c == m){
      #pragma unroll
      for (int u=0; u<K-1; u++) best[u] = best[u+1];
      best[K-1] = 0x7F800000FFFFFFFFull;
    }
    out[s] = m;
  }
}

template<int K, bool SQRT>
__global__ void k_knn_write(const float4* __restrict__ Q, const float4* __restrict__ R,
                            int* __restrict__ oIdx, float* __restrict__ oD){
  int row = blockIdx.x*(blockDim.x>>5) + (threadIdx.x>>5);
  if (row >= BN) return;
  unsigned long long out[K];
  warp_topk<K,false,false,SQRT>(Q, R, nullptr, row, out);
  if ((threadIdx.x & 31) == 0){
    #pragma unroll
    for (int s=0; s<K; s++){
      oIdx[row*K+s] = (int)(out[s] & 0xFFFFFFFFu);
      if (oD) oD[row*K+s] = __uint_as_float((unsigned)(out[s] >> 32));
    }
  }
}

// top-32 unmasked self-KNN of xy1 (once): feeds nbA (prefix 12) + masked-KNN filter lists
__global__ void k_knn32(){
  int row = blockIdx.x*(blockDim.x>>5) + (threadIdx.x>>5);
  if (row >= BN) return;
  unsigned long long out[32];
  warp_topk<32,false,false,false>(g_xy1p, g_xy1p, nullptr, row, out);
  int lane = threadIdx.x & 31;
  if (lane == 0){
    #pragma unroll
    for (int s=0; s<32; s++){
      int jj = (int)(out[s] & 0xFFFFFFFFu);
      g_nn1i[row*32+s] = jj;
      g_nn1d[row*32+s] = __uint_as_float((unsigned)(out[s] >> 32));
      if (s < 12) g_nbA[row*12+s] = jj;
    }
  }
}

// per-batch matched count
__global__ void k_count(const int* __restrict__ m, int* __restrict__ out){
  __shared__ int sh[1024];
  int b = blockIdx.x, tid = threadIdx.x;
  sh[tid] = m[b*N_+tid] + m[b*N_+tid+1024];
  __syncthreads();
  for (int s=512; s; s>>=1){ if (tid < s) sh[tid] += sh[tid+s]; __syncthreads(); }
  if (tid == 0) out[b] = sh[0];
}

// ---------------- feature-cost: one thread per (row, cand) ----------
__global__ void k_kc(){
  int e = blockIdx.x*blockDim.x + threadIdx.x;
  if (e >= BN*4) return;
  int w = e >> 2, c = e & 3;
  int b = w / N_;
  int j = g_cand[w*4+c];
  const float* f1 = g_f1n + (size_t)w*C_;
  const float* f2 = g_f2n + ((size_t)(b*N_ + j))*C_;
  float s = 0.f;
  #pragma unroll 8
  for (int k=0; k<C_; k++) s = __fmaf_rn(f1[k], __ldg(&f2[k]), s);
  float Cmv = __fsub_rn(1.0f, s);
  g_Kc[w*4+c] = expf(__fdiv_rn(-Cmv, g_par[0]));
  if (c == 0){
    int k0 = (g_cand[w*4+0]<<2)|0, k1 = (g_cand[w*4+1]<<2)|1;
    int k2 = (g_cand[w*4+2]<<2)|2, k3 = (g_cand[w*4+3]<<2)|3;
    int t;
    if (k0>k1){t=k0;k0=k1;k1=t;} if (k2>k3){t=k2;k2=k3;k3=t;}
    if (k0>k2){t=k0;k0=k2;k2=t;} if (k1>k3){t=k1;k1=k3;k3=t;}
    if (k1>k2){t=k1;k1=k2;k2=t;}
    g_sord[w] = (k0&3) | ((k1&3)<<2) | ((k2&3)<<4) | ((k3&3)<<6);
  }
}

// ---------------- fused transpose-list build (one block per batch) ----------------
__global__ void k_ctbuild(){
  __shared__ int scnt[N_];
  __shared__ int scur[N_];
  int b = blockIdx.x, tid = threadIdx.x;
  scnt[tid] = 0; scnt[tid+1024] = 0;
  __syncthreads();
  #pragma unroll
  for (int rr=0; rr<2; rr++){
    int i = tid + rr*1024;
    #pragma unroll
    for (int c=0; c<4; c++) atomicAdd(&scnt[g_cand[(b*N_+i)*4+c]], 1);
  }
  __syncthreads();
  if (tid < 32){
    int lo = tid*64, tot = 0;
    for (int t=0; t<64; t++) tot += scnt[lo+t];
    int inc = tot;
    #pragma unroll
    for (int off=1; off<32; off<<=1){
      int v = __shfl_up_sync(0xffffffffu, inc, off);
      if (tid >= off) inc += v;
    }
    int run = inc - tot;
    for (int t=0; t<64; t++){
      g_coff[b*N_+lo+t] = run;
      scur[lo+t] = run;
      g_ccnt[b*N_+lo+t] = scnt[lo+t];
      run += scnt[lo+t];
    }
  }
  __syncthreads();
  #pragma unroll
  for (int rr=0; rr<2; rr++){
    int i = tid + rr*1024;
    #pragma unroll
    for (int c=0; c<4; c++){
      int j = g_cand[(b*N_+i)*4+c];
      int pos = atomicAdd(&scur[j], 1);
      g_tlist[b*N_*4 + pos] = (i<<2) | c;
    }
  }
  __syncthreads();
  #pragma unroll
  for (int rr=0; rr<2; rr++){
    int col = tid + rr*1024;
    int off = g_coff[b*N_+col], cnt = g_ccnt[b*N_+col];
    int* L = g_tlist + b*N_*4 + off;
    for (int a2=1; a2<cnt; a2++){
      int v = L[a2]; int p = a2-1;
      while (p >= 0 && L[p] > v){ L[p+1] = L[p]; p--; }
      L[p+1] = v;
    }
  }
}

// ---------------- fused sparse sinkhorn (5 iters) + mutual-best recon ----------------
__global__ void k_sinkhorn(int dr0){
  __shared__ float su[N_], sv[N_];
  __shared__ unsigned long long ck[N_];
  int b = blockIdx.x, tid = threadIdx.x;
  const int* cb = g_cand + b*N_*4;
  const float* Kb = g_Kc + b*N_*4;
  const int* sob = g_sord + b*N_;
  const int* tl = g_tlist + b*N_*4;
  const float P = 1.0f/2048.0f;
  float pw = g_par[1];

  sv[tid] = 1.f; sv[tid+1024] = 1.f;
  __syncthreads();

  for (int t=0; t<5; t++){
    #pragma unroll
    for (int rr=0; rr<2; rr++){
      int i = tid + rr*1024;
      int o = sob[i];
      float s = 0.f;
      #pragma unroll
      for (int p=0; p<4; p++){
        int sl = (o >> (2*p)) & 3;
        if (sl < dr0)
          s = __fmaf_rn(Kb[i*4+sl], sv[cb[i*4+sl]], s);
      }
      su[i] = powf(__fdiv_rn(P, __fadd_rn(s, EPSF)), pw);
    }
    __syncthreads();
    #pragma unroll
    for (int rr=0; rr<2; rr++){
      int j = tid + rr*1024;
      int off = g_coff[b*N_+j], cnt = g_ccnt[b*N_+j];
      float s = 0.f;
      for (int p=0; p<cnt; p++){
        int e = tl[off+p];
        int c = e & 3;
        if (c < dr0){
          int i = e >> 2;
          s = __fmaf_rn(Kb[i*4+c], su[i], s);
        }
      }
      sv[j] = powf(__fdiv_rn(P, __fadd_rn(s, EPSF)), pw);
    }
    __syncthreads();
  }

  ck[tid] = 0xFFFFFFFFull; ck[tid+1024] = 0xFFFFFFFFull;
  __syncthreads();
  #pragma unroll
  for (int rr=0; rr<2; rr++){
    int i = tid + rr*1024;
    float ui = su[i];
    for (int c=0; c<dr0; c++){
      int j = cb[i*4+c];
      float tv = __fmul_rn(__fmul_rn(ui, Kb[i*4+c]), sv[j]);
      unsigned long long key = ((unsigned long long)__float_as_uint(tv) << 32)
                             | (unsigned)(~(unsigned)i);
      atomicMax(&ck[j], key);
    }
  }
  __syncthreads();
  #pragma unroll
  for (int rr=0; rr<2; rr++){
    int i = tid + rr*1024;
    float ui = su[i];
    unsigned long long k0 = 0ull, k1 = 0ull;
    for (int c=0; c<dr0; c++){
      int j = cb[i*4+c];
      float tv = __fmul_rn(__fmul_rn(ui, Kb[i*4+c]), sv[j]);
      unsigned long long key = ((unsigned long long)__float_as_uint(tv) << 32)
                             | (unsigned)(~(unsigned)j);
      if (key > k0){ k1 = k0; k0 = key; }
      else if (key > k1){ k1 = key; }
    }
    float rv0 = __uint_as_float((unsigned)(k0 >> 32));
    float rv1 = __uint_as_float((unsigned)(k1 >> 32));
    int bj = (int)(~(unsigned)k0);
    int bi = (int)(~(unsigned)ck[bj]);
    bool ok = rv0 > __fmul_rn(1.2f, rv1);
    g_idx0[b*N_ + i] = (bi == i && ok) ? bj : -1;
  }
}

// ---------------- merge (+optional knn recon) + similarity verify ----------------
template<int SIMK, int MODE>
__global__ void k_simmerge(const float* __restrict__ xy1, const float* __restrict__ xy2){
  int row = blockIdx.x*blockDim.x + threadIdx.x;
  if (row >= BN) return;
  int b = row / N_, i = row - b*N_;
  int m;
  if (MODE == 0) m = g_idx0[row];
  else if (MODE == 1){ int p = g_idx1[row]; m = (p == 0) ? g_idx0[row] : (p - 1); }
  else {
    float d0 = g_rowD[row*2], d1 = g_rowD[row*2+1];
    int bj = g_rowIdx[row*2];
    bool ok = __fmul_rn(d0, 1.2f) < d1;
    bool mut = (g_colArg[b*N_ + bj] == i);
    m = (ok && mut) ? bj : -1;
  }

  int outv = -1;
  if (m >= 0){
    const float* X1 = xy1 + (size_t)b*N_*2;
    const float* X2 = xy2 + (size_t)b*N_*2;
    float pix = X1[i*2], piy = X1[i*2+1];
    float pjx = X2[m*2], pjy = X2[m*2+1];
    float o1x[SIMK], o1y[SIMK], o2x[SIMK], o2y[SIMK];
    #pragma unroll
    for (int k=0; k<SIMK; k++){
      int a = g_nbA[row*12 + 1 + k];
      o1x[k] = __fsub_rn(X1[a*2],   pix);
      o1y[k] = __fsub_rn(X1[a*2+1], piy);
      int c = g_nbB[(b*N_+m)*12 + 1 + k];
      o2x[k] = __fsub_rn(X2[c*2],   pjx);
      o2y[k] = __fsub_rn(X2[c*2+1], pjy);
    }
    float colmin[SIMK];
    #pragma unroll
    for (int l=0; l<SIMK; l++) colmin[l] = 3.4e38f;
    float sum1 = 0.f;
    #pragma unroll
    for (int k=0; k<SIMK; k++){
      float rmn = 3.4e38f;
      #pragma unroll
      for (int l=0; l<SIMK; l++){
        float dx = __fsub_rn(o1x[k], o2x[l]);
        float dy = __fsub_rn(o1y[k], o2y[l]);
        float d = sqrtf(__fadd_rn(__fmaf_rn(dy, dy, __fmul_rn(dx, dx)), EPSF));
        rmn = fminf(rmn, d);
        colmin[l] = fminf(colmin[l], d);
      }
      sum1 = __fadd_rn(sum1, rmn);
    }
    float sum2 = 0.f;
    #pragma unroll
    for (int l=0; l<SIMK; l++) sum2 = __fadd_rn(sum2, colmin[l]);
    float Kf = (float)SIMK;
    float cham = __fmul_rn(0.5f, __fadd_rn(__fdiv_rn(sum1, Kf), __fdiv_rn(sum2, Kf)));
    if (cham <= 2.0f) outv = m;
  }
  g_idxA[row] = outv;
  int mm = (outv >= 0);
  g_maskA[row] = mm;
  int j = (outv >= 0) ? outv : 0;
  float mf = (float)mm;
  g_flow[row*2]   = __fmul_rn(__fsub_rn(xy2[(b*N_+j)*2],   xy1[row*2]),   mf);
  g_flow[row*2+1] = __fmul_rn(__fsub_rn(xy2[(b*N_+j)*2+1], xy1[row*2+1]), mf);
}

// ---------------- masked KNN(8) via filter list (+rare fallback) + outlier ----------
__global__ void k_outlier_fast(){
  int row = blockIdx.x*(blockDim.x>>5) + (threadIdx.x>>5);
  if (row >= BN) return;
  int lane = threadIdx.x & 31;
  int b = row / N_, i = row - b*N_;

  int idx = g_nn1i[row*32+lane];
  float d2 = g_nn1d[row*32+lane];
  int mi = g_maskA[row];
  bool okm = (g_maskA[b*N_+idx] != 0) && (idx != i);
  unsigned bal = __ballot_sync(0xffffffffu, okm);
  int avail = __popc(bal);
  int total = g_cntA[b] - mi;
  int needed = total < 8 ? total : 8;

  unsigned long long out[8];
  if (avail >= needed){
    unsigned rem = bal;
    #pragma unroll
    for (int s=0; s<8; s++){
      if (rem){
        int l = __ffs(rem) - 1; rem &= rem - 1;
        float dd = __shfl_sync(0xffffffffu, d2, l);
        int jj = __shfl_sync(0xffffffffu, idx, l);
        out[s] = ((unsigned long long)__float_as_uint(dd) << 32) | (unsigned)jj;
      } else out[s] = 0x7F800000FFFFFFFFull;
    }
  } else {
    warp_topk<8,true,true,false>(g_xy1p, g_xy1p, g_maskA, row, out);
  }

  if (lane == 0){
    float fx = g_flow[row*2], fy = g_flow[row*2+1];
    float sx = 0.f, sy = 0.f, cnt = 0.f;
    #pragma unroll
    for (int s=0; s<8; s++){
      float d = __uint_as_float((unsigned)(out[s] >> 32));
      int j = (int)(out[s] & 0xFFFFFFFFu);
      float vf = (d < 5e8f) ? 1.0f : 0.0f;
      sx = __fmaf_rn(g_flow[(b*N_+j)*2],   vf, sx);
      sy = __fmaf_rn(g_flow[(b*N_+j)*2+1], vf, sy);
      cnt = __fadd_rn(cnt, vf);
    }
    float dv = fmaxf(cnt, 1.0f);
    float mx = __fdiv_rn(sx, dv), my = __fdiv_rn(sy, dv);
    float ddx = __fsub_rn(fx, mx), ddy = __fsub_rn(fy, my);
    float dev = sqrtf(__fadd_rn(__fmaf_rn(ddy, ddy, __fmul_rn(ddx, ddx)), EPSF));
    bool keep = mi && ((cnt > 0.0f) ? (dev <= 2.0f) : true);
    g_idx1[row] = keep ? (g_idxA[row] + 1) : 0;
  }
}

__global__ void k_dedup(){
  __shared__ int cnt[N_+1];
  int b = blockIdx.x, tid = threadIdx.x;
  for (int s = tid; s < N_+1; s += 1024) cnt[s] = 0;
  __syncthreads();
  int v0 = g_idx1[b*N_ + tid], v1 = g_idx1[b*N_ + tid + 1024];
  atomicAdd(&cnt[v0], 1); atomicAdd(&cnt[v1], 1);
  __syncthreads();
  if (cnt[v0] > 1) g_idx1[b*N_ + tid] = 0;
  if (cnt[v1] > 1) g_idx1[b*N_ + tid + 1024] = 0;
}

__global__ void k_finish(const float* __restrict__ xy1, const float* __restrict__ xy2,
                         float* __restrict__ outp, int withmask){
  int row = blockIdx.x*blockDim.x + threadIdx.x;
  if (row >= BN) return;
  int b = row / N_;
  int v = g_idx1[row];
  int mm = (v != 0);
  int j = (v - 1) * mm;
  float mf = (float)mm;
  float fx = __fmul_rn(__fsub_rn(xy2[(b*N_+j)*2],   xy1[row*2]),   mf);
  float fy = __fmul_rn(__fsub_rn(xy2[(b*N_+j)*2+1], xy1[row*2+1]), mf);
  g_flow[row*2] = fx; g_flow[row*2+1] = fy;
  g_mask[row] = mm;
  if (outp){
    outp[row*2] = fx; outp[row*2+1] = fy;
    if (withmask) outp[2*BN + row] = mf;
  }
}

// ---------------- masked KNN(4) via filter list (+rare fallback) + IDW -------------
__global__ void k_griddata_fast(){
  int row = blockIdx.x*(blockDim.x>>5) + (threadIdx.x>>5);
  if (row >= BN) return;
  int lane = threadIdx.x & 31;
  int b = row / N_;

  int idx = g_nn1i[row*32+lane];
  float d2 = g_nn1d[row*32+lane];
  bool okm = (g_mask[b*N_+idx] != 0);
  unsigned bal = __ballot_sync(0xffffffffu, okm);
  int avail = __popc(bal);
  int total = g_cntM[b];
  int needed = total < 4 ? total : 4;

  unsigned long long out[4];
  if (avail >= needed){
    unsigned rem = bal;
    #pragma unroll
    for (int s=0; s<4; s++){
      if (rem){
        int l = __ffs(rem) - 1; rem &= rem - 1;
        float dd = __shfl_sync(0xffffffffu, d2, l);
        int jj = __shfl_sync(0xffffffffu, idx, l);
        out[s] = ((unsigned long long)__float_as_uint(dd) << 32) | (unsigned)jj;
      } else out[s] = 0x7F800000FFFFFFFFull;
    }
  } else {
    warp_topk<4,true,false,false>(g_xy1p, g_xy1p, g_mask, row, out);
  }

  if (lane == 0){
    float ws = 0.f, sx = 0.f, sy = 0.f;
    #pragma unroll
    for (int s=0; s<4; s++){
      float d = __uint_as_float((unsigned)(out[s] >> 32));
      int j = (int)(out[s] & 0xFFFFFFFFu);
      float vf = (d < 5e8f) ? 1.0f : 0.0f;
      float w = __fdiv_rn(vf, __fadd_rn(d, 1e-6f));
      sx = __fmaf_rn(w, g_flow[(b*N_+j)*2],   sx);
      sy = __fmaf_rn(w, g_flow[(b*N_+j)*2+1], sy);
      ws = __fadd_rn(ws, w);
    }
    float ix = __fdiv_rn(sx, __fadd_rn(ws, EPSF));
    float iy = __fdiv_rn(sy, __fadd_rn(ws, EPSF));
    int m = g_mask[row];
    g_fgri[row*2]   = m ? g_flow[row*2]   : ix;
    g_fgri[row*2+1] = m ? g_flow[row*2+1] : iy;
  }
}

// ---------------- host orchestration ----------------
extern "C" void kernel_launch(void* const* d_in, const int* in_sizes, int n_in,
                              void* d_out, int out_size){
  const float* xy1 = (const float*)d_in[0];
  const float* xy2 = (const float*)d_in[1];
  const float* f1  = (const float*)d_in[2];
  const float* f2  = (const float*)d_in[3];
  const float* gam = (const float*)d_in[4];
  const float* eps = (const float*)d_in[5];
  float* outp = (float*)d_out;
  int withmask = (out_size >= BN*3) ? 1 : 0;

  float4 *p_xy1p, *p_xy2p, *p_xy11p;
  float *p_rowD;
  int *p_nbB, *p_cand, *p_rowIdx, *p_colArg, *p_maskA, *p_mask, *p_cntA, *p_cntM;
  cudaGetSymbolAddress((void**)&p_xy1p,   g_xy1p);
  cudaGetSymbolAddress((void**)&p_xy2p,   g_xy2p);
  cudaGetSymbolAddress((void**)&p_xy11p,  g_xy11p);
  cudaGetSymbolAddress((void**)&p_nbB,    g_nbB);
  cudaGetSymbolAddress((void**)&p_cand,   g_cand);
  cudaGetSymbolAddress((void**)&p_rowD,   g_rowD);
  cudaGetSymbolAddress((void**)&p_rowIdx, g_rowIdx);
  cudaGetSymbolAddress((void**)&p_colArg, g_colArg);
  cudaGetSymbolAddress((void**)&p_maskA,  g_maskA);
  cudaGetSymbolAddress((void**)&p_mask,   g_mask);
  cudaGetSymbolAddress((void**)&p_cntA,   g_cntA);
  cudaGetSymbolAddress((void**)&p_cntM,   g_cntM);

  const int WB = 256;
  const int GW = BN/8;
  const int TB = 256, GT = (BN+TB-1)/TB;

  k_params<<<1,1>>>(gam, eps);
  k_norms<<<(2*BN*32)/256, 256>>>(f1, f2);
  k_normalize<<<(2*BN*C_ + 255)/256, 256>>>(f1, f2);
  k_prep<<<GT, TB>>>(xy1, p_xy1p, 0);
  k_prep<<<GT, TB>>>(xy2, p_xy2p, 0);
  k_knn32<<<GW, WB>>>();                                    // xy1 self top-32 (+nbA)
  k_knn_write<12,false><<<GW, WB>>>(p_xy2p, p_xy2p, p_nbB, nullptr);

  // ---- two sinkhorn matching passes ----
  for (int pass = 0; pass < 2; pass++){
    const float4* qp = p_xy1p;
    if (pass){ k_prep<<<GT, TB>>>(xy1, p_xy11p, 1); qp = p_xy11p; }
    k_knn_write<4,false><<<GW, WB>>>(qp, p_xy2p, p_cand, nullptr);
    k_kc<<<(BN*4+127)/128, 128>>>();
    k_ctbuild<<<B_, 1024>>>();
    for (int r = 0; r < 4; r++){
      k_sinkhorn<<<2, 1024>>>(r + 1);
      if (r == 0) k_simmerge<8,0><<<GT, TB>>>(xy1, xy2);
      else        k_simmerge<8,1><<<GT, TB>>>(xy1, xy2);
      k_count<<<B_, 1024>>>(p_maskA, p_cntA);
      k_outlier_fast<<<GW, WB>>>();
      if (r > 0) k_dedup<<<2, 1024>>>();
    }
    k_finish<<<GT, TB>>>(xy1, xy2, nullptr, 0);
    k_count<<<B_, 1024>>>(p_mask, p_cntM);
    k_griddata_fast<<<GW, WB>>>();
  }

  // ---- two KNN matching passes ----
  for (int pass = 0; pass < 2; pass++){
    int final = (pass == 1);
    k_prep<<<GT, TB>>>(xy1, p_xy11p, 1);
    k_knn_write<2,true><<<GW, WB>>>(p_xy11p, p_xy2p, p_rowIdx, p_rowD);
    k_knn_write<1,true><<<GW, WB>>>(p_xy2p, p_xy11p, p_colArg, nullptr);
    k_simmerge<11,2><<<GT, TB>>>(xy1, xy2);
    k_count<<<B_, 1024>>>(p_maskA, p_cntA);
    k_outlier_fast<<<GW, WB>>>();
    k_finish<<<GT, TB>>>(xy1, xy2, final ? outp : nullptr, withmask);
    if (!final){
      k_count<<<B_, 1024>>>(p_mask, p_cntM);
      k_griddata_fast<<<GW, WB>>>();
    }
  }
}

// round 7
// speedup vs baseline: 1.0666x; 1.0666x over previous
#include <cuda_runtime.h>
#include <stdint.h>
#include <math.h>

#define N_   2048
#define B_   2
#define C_   512
#define BN   (B_*N_)
#define EPSF 1e-8f
#define BIGF 1e9f
#define G_   32
#define NC_  (G_*G_)

// ---------------- device scratch ----------------
__device__ float  g_nrm1[BN], g_nrm2[BN];
__device__ float  g_f1n[BN*C_], g_f2n[BN*C_];
__device__ float4 g_xy1p[BN], g_xy2p[BN], g_xy11p[BN];   // (x, y, rb, 0)
__device__ int    g_nbA[BN*12], g_nbB[BN*12];
__device__ int    g_cand[BN*4];
__device__ float  g_Kc[BN*4];
__device__ int    g_sord[BN];
__device__ int    g_ccnt[B_*N_], g_coff[B_*N_];
__device__ int    g_tlist[B_*N_*4];
__device__ int    g_idx0[BN], g_idxA[BN], g_maskA[BN], g_idx1[BN], g_mask[BN];
__device__ float  g_flow[BN*2], g_fgri[BN*2];
__device__ float  g_rowD[BN*2];
__device__ int    g_rowIdx[BN*2];
__device__ int    g_colArg[BN];
__device__ float  g_par[2];
// grids: params (minx,miny,invhx,invhy),(hx,hy,-,-); cell starts; point lists
__device__ float4 g_gp1[B_*2],  g_gp2[B_*2],  g_gp11[B_*2];
__device__ int    g_cs1[B_*(NC_+1)], g_cs2[B_*(NC_+1)], g_cs11[B_*(NC_+1)];
__device__ int    g_pl1[BN], g_pl2[BN], g_pl11[BN];

__global__ void k_params(const float* gam, const float* eps){
  float e = __fadd_rn(expf(eps[0]), 0.03f);
  float g = expf(gam[0]);
  g_par[0] = e;
  g_par[1] = __fdiv_rn(g, __fadd_rn(g, e));
}

__global__ void k_norms(const float* __restrict__ f1, const float* __restrict__ f2){
  int w = (blockIdx.x*blockDim.x + threadIdx.x) >> 5;
  int lane = threadIdx.x & 31;
  if (w >= 2*BN) return;
  const float* f = (w < BN) ? (f1 + (size_t)w*C_) : (f2 + (size_t)(w-BN)*C_);
  float s = 0.f;
  for (int c = lane; c < C_; c += 32) s = __fmaf_rn(f[c], f[c], s);
  #pragma unroll
  for (int off=16; off; off>>=1) s = __fadd_rn(s, __shfl_xor_sync(0xffffffffu, s, off));
  if (lane == 0){
    float n = __fadd_rn(sqrtf(s), EPSF);
    if (w < BN) g_nrm1[w] = n; else g_nrm2[w-BN] = n;
  }
}

__global__ void k_normalize(const float* __restrict__ f1, const float* __restrict__ f2){
  int e = blockIdx.x*blockDim.x + threadIdx.x;
  const int tot = BN*C_;
  if (e < tot){
    g_f1n[e] = __fdiv_rn(f1[e], g_nrm1[e / C_]);
  } else if (e < 2*tot){
    int e2 = e - tot;
    g_f2n[e2] = __fdiv_rn(f2[e2], g_nrm2[e2 / C_]);
  }
}

__global__ void k_prep(const float* __restrict__ xy, float4* __restrict__ dst, int addflow){
  int p = blockIdx.x*blockDim.x + threadIdx.x;
  if (p >= BN) return;
  float x = xy[p*2], y = xy[p*2+1];
  if (addflow){ x = __fadd_rn(x, g_fgri[p*2]); y = __fadd_rn(y, g_fgri[p*2+1]); }
  dst[p] = make_float4(x, y, __fmaf_rn(y, y, __fmul_rn(x, x)), 0.f);
}

// ---------------- grid build: one block per batch ----------------
__global__ void k_gridbuild(const float4* __restrict__ pts, float4* __restrict__ gp,
                            int* __restrict__ cs, int* __restrict__ pl){
  __shared__ float sred[1024];
  __shared__ int   scnt[NC_], soff[NC_];
  __shared__ float sbb[4];   // minx, maxx, miny, maxy
  int b = blockIdx.x, tid = threadIdx.x;   // 1024 threads
  float4 a = pts[b*N_+tid], c = pts[b*N_+tid+1024];

  sred[tid] = fminf(a.x, c.x); __syncthreads();
  for (int s=512; s; s>>=1){ if (tid<s) sred[tid] = fminf(sred[tid], sred[tid+s]); __syncthreads(); }
  if (!tid) sbb[0] = sred[0]; __syncthreads();
  sred[tid] = fmaxf(a.x, c.x); __syncthreads();
  for (int s=512; s; s>>=1){ if (tid<s) sred[tid] = fmaxf(sred[tid], sred[tid+s]); __syncthreads(); }
  if (!tid) sbb[1] = sred[0]; __syncthreads();
  sred[tid] = fminf(a.y, c.y); __syncthreads();
  for (int s=512; s; s>>=1){ if (tid<s) sred[tid] = fminf(sred[tid], sred[tid+s]); __syncthreads(); }
  if (!tid) sbb[2] = sred[0]; __syncthreads();
  sred[tid] = fmaxf(a.y, c.y); __syncthreads();
  for (int s=512; s; s>>=1){ if (tid<s) sred[tid] = fmaxf(sred[tid], sred[tid+s]); __syncthreads(); }
  if (!tid){
    sbb[3] = sred[0];
    float ex = sbb[1]-sbb[0], ey = sbb[3]-sbb[2];
    float ihx = ex > 1e-20f ? (float)G_/ex : 0.f;
    float ihy = ey > 1e-20f ? (float)G_/ey : 0.f;
    gp[b*2+0] = make_float4(sbb[0], sbb[2], ihx, ihy);
    gp[b*2+1] = make_float4(ex/(float)G_, ey/(float)G_, 0.f, 0.f);
  }
  __syncthreads();
  float minx = sbb[0], miny = sbb[2];
  float ihx = gp[b*2].z, ihy = gp[b*2].w;

  scnt[tid] = 0; __syncthreads();
  int cax = (int)((a.x-minx)*ihx); cax = cax<0?0:(cax>G_-1?G_-1:cax);
  int cay = (int)((a.y-miny)*ihy); cay = cay<0?0:(cay>G_-1?G_-1:cay);
  int ccx = (int)((c.x-minx)*ihx); ccx = ccx<0?0:(ccx>G_-1?G_-1:ccx);
  int ccy = (int)((c.y-miny)*ihy); ccy = ccy<0?0:(ccy>G_-1?G_-1:ccy);
  int cellA = cay*G_+cax, cellC = ccy*G_+ccx;
  atomicAdd(&scnt[cellA], 1); atomicAdd(&scnt[cellC], 1);
  __syncthreads();
  if (tid < 32){
    int lo = tid*32, tot = 0;
    for (int t=0; t<32; t++) tot += scnt[lo+t];
    int inc = tot;
    #pragma unroll
    for (int off=1; off<32; off<<=1){
      int v = __shfl_up_sync(0xffffffffu, inc, off);
      if (tid >= off) inc += v;
    }
    int run = inc - tot;
    for (int t=0; t<32; t++){ soff[lo+t] = run; run += scnt[lo+t]; }
  }
  __syncthreads();
  cs[b*(NC_+1)+tid] = soff[tid];
  if (tid == 0) cs[b*(NC_+1)+NC_] = N_;
  scnt[tid] = soff[tid]; __syncthreads();
  int pA = atomicAdd(&scnt[cellA], 1); pl[b*N_+pA] = tid;
  int pC = atomicAdd(&scnt[cellC], 1); pl[b*N_+pC] = tid + 1024;
}

// ---------------- exact grid KNN (thread per query) ----------------
template<int K, bool MASK, bool EYE, bool SQRT>
__device__ __forceinline__ void grid_knn(
    int b, int i, float qx, float qy,
    const float4* __restrict__ gp, const int* __restrict__ cs,
    const int* __restrict__ pl, const float4* __restrict__ pts,
    const int* __restrict__ mask, unsigned long long (&best)[K])
{
  const unsigned long long INFK = 0x7F800000FFFFFFFFull;
  #pragma unroll
  for (int s=0; s<K; s++) best[s] = INFK;
  float4 p0 = gp[b*2+0];  // minx,miny,invhx,invhy
  float4 p1 = gp[b*2+1];  // hx,hy
  float qa = __fmaf_rn(qy, qy, __fmul_rn(qx, qx));
  int qcx = (int)((qx - p0.x)*p0.z); qcx = qcx<0?0:(qcx>G_-1?G_-1:qcx);
  int qcy = (int)((qy - p0.y)*p0.w); qcy = qcy<0?0:(qcy>G_-1?G_-1:qcy);
  const int* csb = cs + b*(NC_+1);
  const int* plb = pl + b*N_;
  const float4* ptsb = pts + (size_t)b*N_;
  const int* mb = MASK ? (mask + b*N_) : nullptr;

  for (int r=0; r<=G_; r++){
    int xlo = qcx-r<0?0:qcx-r, xhi = qcx+r>G_-1?G_-1:qcx+r;
    int ylo = qcy-r<0?0:qcy-r, yhi = qcy+r>G_-1?G_-1:qcy+r;

    auto visit = [&](int cx, int cy){
      int cc = cy*G_ + cx;
      int s0 = __ldg(&csb[cc]), e0 = __ldg(&csb[cc+1]);
      for (int p=s0; p<e0; p++){
        int j = __ldg(&plb[p]);
        if (EYE){ if (j == i) continue; }
        if (MASK){ if (!__ldg(&mb[j])) continue; }
        float4 rr = __ldg(&ptsb[j]);
        float dt = __fmaf_rn(qy, rr.y, __fmul_rn(qx, rr.x));
        float d  = fmaxf(__fsub_rn(__fadd_rn(qa, rr.z), __fmul_rn(2.0f, dt)), 0.0f);
        if (SQRT) d = sqrtf(__fadd_rn(d, EPSF));
        unsigned long long key = ((unsigned long long)__float_as_uint(d) << 32) | (unsigned)j;
        if (key < best[K-1]){
          best[K-1] = key;
          #pragma unroll
          for (int s2=K-1; s2>0; s2--){
            if (best[s2] < best[s2-1]){
              unsigned long long t = best[s2-1]; best[s2-1] = best[s2]; best[s2] = t;
            } else break;
          }
        }
      }
    };

    if (r == 0){
      visit(qcx, qcy);
    } else {
      if (qcy-r >= 0)     for (int cx=xlo; cx<=xhi; cx++) visit(cx, qcy-r);
      if (qcy+r <= G_-1)  for (int cx=xlo; cx<=xhi; cx++) visit(cx, qcy+r);
      int yl2 = ylo > qcy-r+1 ? ylo : qcy-r+1;
      int yh2 = yhi < qcy+r-1 ? yhi : qcy+r-1;
      if (qcx-r >= 0)     for (int cy=yl2; cy<=yh2; cy++) visit(qcx-r, cy);
      if (qcx+r <= G_-1)  for (int cy=yl2; cy<=yh2; cy++) visit(qcx+r, cy);
    }

    bool cover = (qcx-r <= 0) && (qcx+r >= G_-1) && (qcy-r <= 0) && (qcy+r >= G_-1);
    if (cover) break;
    if (best[K-1] != INFK){
      float kd = __uint_as_float((unsigned)(best[K-1] >> 32));
      float lb = 3.4e38f;
      if (qcx+r+1 <= G_-1) lb = fminf(lb, __fmaf_rn((float)(qcx+r+1), p1.x, p0.x) - qx);
      if (qcx-r   >= 1)    lb = fminf(lb, qx - __fmaf_rn((float)(qcx-r),   p1.x, p0.x));
      if (qcy+r+1 <= G_-1) lb = fminf(lb, __fmaf_rn((float)(qcy+r+1), p1.y, p0.y) - qy);
      if (qcy-r   >= 1)    lb = fminf(lb, qy - __fmaf_rn((float)(qcy-r),   p1.y, p0.y));
      lb = fmaxf(lb, 0.f);
      // conservative: unvisited computed d2 >= 0.996*lb^2 - 0.05 (abs cancellation slack)
      float lb2 = 0.996f*lb*lb - 0.05f;
      bool stop;
      if (SQRT) stop = (kd < 0.999f*sqrtf(fmaxf(lb2, 0.f) + EPSF));
      else      stop = (kd < lb2);
      if (stop) break;
    }
  }
}

template<int K, bool SQRT>
__global__ void k_gknn(const float4* __restrict__ Q,
                       const float4* __restrict__ gp, const int* __restrict__ cs,
                       const int* __restrict__ pl, const float4* __restrict__ pts,
                       int* __restrict__ oIdx, float* __restrict__ oD){
  int row = blockIdx.x*blockDim.x + threadIdx.x;
  if (row >= BN) return;
  int b = row / N_;
  float4 q = __ldg(&Q[row]);
  unsigned long long out[K];
  grid_knn<K,false,false,SQRT>(b, -1, q.x, q.y, gp, cs, pl, pts, nullptr, out);
  #pragma unroll
  for (int s=0; s<K; s++){
    oIdx[row*K+s] = (int)(out[s] & 0xFFFFFFFFu);
    if (oD) oD[row*K+s] = __uint_as_float((unsigned)(out[s] >> 32));
  }
}

// ---------------- feature-cost (float4 loads, same accumulation order) ----------
__global__ void k_kc(){
  int e = blockIdx.x*blockDim.x + threadIdx.x;
  if (e >= BN*4) return;
  int w = e >> 2, c = e & 3;
  int b = w / N_;
  int j = g_cand[w*4+c];
  const float4* f1 = (const float4*)(g_f1n + (size_t)w*C_);
  const float4* f2 = (const float4*)(g_f2n + ((size_t)(b*N_ + j))*C_);
  float s = 0.f;
  #pragma unroll 4
  for (int k=0; k<C_/4; k++){
    float4 A = f1[k], Bv = __ldg(&f2[k]);
    s = __fmaf_rn(A.x, Bv.x, s);
    s = __fmaf_rn(A.y, Bv.y, s);
    s = __fmaf_rn(A.z, Bv.z, s);
    s = __fmaf_rn(A.w, Bv.w, s);
  }
  float Cmv = __fsub_rn(1.0f, s);
  g_Kc[w*4+c] = expf(__fdiv_rn(-Cmv, g_par[0]));
  if (c == 0){
    int k0 = (g_cand[w*4+0]<<2)|0, k1 = (g_cand[w*4+1]<<2)|1;
    int k2 = (g_cand[w*4+2]<<2)|2, k3 = (g_cand[w*4+3]<<2)|3;
    int t;
    if (k0>k1){t=k0;k0=k1;k1=t;} if (k2>k3){t=k2;k2=k3;k3=t;}
    if (k0>k2){t=k0;k0=k2;k2=t;} if (k1>k3){t=k1;k1=k3;k3=t;}
    if (k1>k2){t=k1;k1=k2;k2=t;}
    g_sord[w] = (k0&3) | ((k1&3)<<2) | ((k2&3)<<4) | ((k3&3)<<6);
  }
}

// ---------------- transpose-list build (one block per batch) ----------------
__global__ void k_ctbuild(){
  __shared__ int scnt[N_];
  __shared__ int scur[N_];
  int b = blockIdx.x, tid = threadIdx.x;
  scnt[tid] = 0; scnt[tid+1024] = 0;
  __syncthreads();
  #pragma unroll
  for (int rr=0; rr<2; rr++){
    int i = tid + rr*1024;
    #pragma unroll
    for (int c=0; c<4; c++) atomicAdd(&scnt[g_cand[(b*N_+i)*4+c]], 1);
  }
  __syncthreads();
  if (tid < 32){
    int lo = tid*64, tot = 0;
    for (int t=0; t<64; t++) tot += scnt[lo+t];
    int inc = tot;
    #pragma unroll
    for (int off=1; off<32; off<<=1){
      int v = __shfl_up_sync(0xffffffffu, inc, off);
      if (tid >= off) inc += v;
    }
    int run = inc - tot;
    for (int t=0; t<64; t++){
      g_coff[b*N_+lo+t] = run;
      scur[lo+t] = run;
      g_ccnt[b*N_+lo+t] = scnt[lo+t];
      run += scnt[lo+t];
    }
  }
  __syncthreads();
  #pragma unroll
  for (int rr=0; rr<2; rr++){
    int i = tid + rr*1024;
    #pragma unroll
    for (int c=0; c<4; c++){
      int j = g_cand[(b*N_+i)*4+c];
      int pos = atomicAdd(&scur[j], 1);
      g_tlist[b*N_*4 + pos] = (i<<2) | c;
    }
  }
  __syncthreads();
  #pragma unroll
  for (int rr=0; rr<2; rr++){
    int col = tid + rr*1024;
    int off = g_coff[b*N_+col], cnt = g_ccnt[b*N_+col];
    int* L = g_tlist + b*N_*4 + off;
    for (int a2=1; a2<cnt; a2++){
      int v = L[a2]; int p = a2-1;
      while (p >= 0 && L[p] > v){ L[p+1] = L[p]; p--; }
      L[p+1] = v;
    }
  }
}

// ---------------- fused sparse sinkhorn (5 iters) + mutual-best recon ----------------
__global__ void k_sinkhorn(int dr0){
  __shared__ float su[N_], sv[N_];
  __shared__ unsigned long long ck[N_];
  int b = blockIdx.x, tid = threadIdx.x;
  const int* cb = g_cand + b*N_*4;
  const float* Kb = g_Kc + b*N_*4;
  const int* sob = g_sord + b*N_;
  const int* tl = g_tlist + b*N_*4;
  const float P = 1.0f/2048.0f;
  float pw = g_par[1];

  sv[tid] = 1.f; sv[tid+1024] = 1.f;
  __syncthreads();

  for (int t=0; t<5; t++){
    #pragma unroll
    for (int rr=0; rr<2; rr++){
      int i = tid + rr*1024;
      int o = sob[i];
      float s = 0.f;
      #pragma unroll
      for (int p=0; p<4; p++){
        int sl = (o >> (2*p)) & 3;
        if (sl < dr0)
          s = __fmaf_rn(Kb[i*4+sl], sv[cb[i*4+sl]], s);
      }
      su[i] = powf(__fdiv_rn(P, __fadd_rn(s, EPSF)), pw);
    }
    __syncthreads();
    #pragma unroll
    for (int rr=0; rr<2; rr++){
      int j = tid + rr*1024;
      int off = g_coff[b*N_+j], cnt = g_ccnt[b*N_+j];
      float s = 0.f;
      for (int p=0; p<cnt; p++){
        int e = tl[off+p];
        int c = e & 3;
        if (c < dr0){
          int i = e >> 2;
          s = __fmaf_rn(Kb[i*4+c], su[i], s);
        }
      }
      sv[j] = powf(__fdiv_rn(P, __fadd_rn(s, EPSF)), pw);
    }
    __syncthreads();
  }

  ck[tid] = 0xFFFFFFFFull; ck[tid+1024] = 0xFFFFFFFFull;
  __syncthreads();
  #pragma unroll
  for (int rr=0; rr<2; rr++){
    int i = tid + rr*1024;
    float ui = su[i];
    for (int c=0; c<dr0; c++){
      int j = cb[i*4+c];
      float tv = __fmul_rn(__fmul_rn(ui, Kb[i*4+c]), sv[j]);
      unsigned long long key = ((unsigned long long)__float_as_uint(tv) << 32)
                             | (unsigned)(~(unsigned)i);
      atomicMax(&ck[j], key);
    }
  }
  __syncthreads();
  #pragma unroll
  for (int rr=0; rr<2; rr++){
    int i = tid + rr*1024;
    float ui = su[i];
    unsigned long long k0 = 0ull, k1 = 0ull;
    for (int c=0; c<dr0; c++){
      int j = cb[i*4+c];
      float tv = __fmul_rn(__fmul_rn(ui, Kb[i*4+c]), sv[j]);
      unsigned long long key = ((unsigned long long)__float_as_uint(tv) << 32)
                             | (unsigned)(~(unsigned)j);
      if (key > k0){ k1 = k0; k0 = key; }
      else if (key > k1){ k1 = key; }
    }
    float rv0 = __uint_as_float((unsigned)(k0 >> 32));
    float rv1 = __uint_as_float((unsigned)(k1 >> 32));
    int bj = (int)(~(unsigned)k0);
    int bi = (int)(~(unsigned)ck[bj]);
    bool ok = rv0 > __fmul_rn(1.2f, rv1);
    g_idx0[b*N_ + i] = (bi == i && ok) ? bj : -1;
  }
}

// ---------------- merge (+optional knn recon) + similarity verify ----------------
template<int SIMK, int MODE>
__global__ void k_simmerge(const float* __restrict__ xy1, const float* __restrict__ xy2){
  int row = blockIdx.x*blockDim.x + threadIdx.x;
  if (row >= BN) return;
  int b = row / N_, i = row - b*N_;
  int m;
  if (MODE == 0) m = g_idx0[row];
  else if (MODE == 1){ int p = g_idx1[row]; m = (p == 0) ? g_idx0[row] : (p - 1); }
  else {
    float d0 = g_rowD[row*2], d1 = g_rowD[row*2+1];
    int bj = g_rowIdx[row*2];
    bool ok = __fmul_rn(d0, 1.2f) < d1;
    bool mut = (g_colArg[b*N_ + bj] == i);
    m = (ok && mut) ? bj : -1;
  }

  int outv = -1;
  if (m >= 0){
    const float* X1 = xy1 + (size_t)b*N_*2;
    const float* X2 = xy2 + (size_t)b*N_*2;
    float pix = X1[i*2], piy = X1[i*2+1];
    float pjx = X2[m*2], pjy = X2[m*2+1];
    float o1x[SIMK], o1y[SIMK], o2x[SIMK], o2y[SIMK];
    #pragma unroll
    for (int k=0; k<SIMK; k++){
      int a = g_nbA[row*12 + 1 + k];
      o1x[k] = __fsub_rn(X1[a*2],   pix);
      o1y[k] = __fsub_rn(X1[a*2+1], piy);
      int c = g_nbB[(b*N_+m)*12 + 1 + k];
      o2x[k] = __fsub_rn(X2[c*2],   pjx);
      o2y[k] = __fsub_rn(X2[c*2+1], pjy);
    }
    float colmin[SIMK];
    #pragma unroll
    for (int l=0; l<SIMK; l++) colmin[l] = 3.4e38f;
    float sum1 = 0.f;
    #pragma unroll
    for (int k=0; k<SIMK; k++){
      float rmn = 3.4e38f;
      #pragma unroll
      for (int l=0; l<SIMK; l++){
        float dx = __fsub_rn(o1x[k], o2x[l]);
        float dy = __fsub_rn(o1y[k], o2y[l]);
        float d = sqrtf(__fadd_rn(__fmaf_rn(dy, dy, __fmul_rn(dx, dx)), EPSF));
        rmn = fminf(rmn, d);
        colmin[l] = fminf(colmin[l], d);
      }
      sum1 = __fadd_rn(sum1, rmn);
    }
    float sum2 = 0.f;
    #pragma unroll
    for (int l=0; l<SIMK; l++) sum2 = __fadd_rn(sum2, colmin[l]);
    float Kf = (float)SIMK;
    float cham = __fmul_rn(0.5f, __fadd_rn(__fdiv_rn(sum1, Kf), __fdiv_rn(sum2, Kf)));
    if (cham <= 2.0f) outv = m;
  }
  g_idxA[row] = outv;
  int mm = (outv >= 0);
  g_maskA[row] = mm;
  int j = (outv >= 0) ? outv : 0;
  float mf = (float)mm;
  g_flow[row*2]   = __fmul_rn(__fsub_rn(xy2[(b*N_+j)*2],   xy1[row*2]),   mf);
  g_flow[row*2+1] = __fmul_rn(__fsub_rn(xy2[(b*N_+j)*2+1], xy1[row*2+1]), mf);
}

// ---------------- masked grid KNN(8)+eye + outlier rejection ----------
__global__ void k_goutlier(){
  int row = blockIdx.x*blockDim.x + threadIdx.x;
  if (row >= BN) return;
  int b = row / N_, i = row - b*N_;
  float4 q = g_xy1p[row];
  unsigned long long out[8];
  grid_knn<8,true,true,false>(b, i, q.x, q.y, g_gp1, g_cs1, g_pl1, g_xy1p, g_maskA, out);

  float fx = g_flow[row*2], fy = g_flow[row*2+1];
  float sx = 0.f, sy = 0.f, cnt = 0.f;
  #pragma unroll
  for (int s=0; s<8; s++){
    float d = __uint_as_float((unsigned)(out[s] >> 32));
    float vf = (d < 5e8f) ? 1.0f : 0.0f;
    int j = (d < 5e8f) ? (int)(out[s] & 0xFFFFFFFFu) : 0;
    sx = __fmaf_rn(g_flow[(b*N_+j)*2],   vf, sx);
    sy = __fmaf_rn(g_flow[(b*N_+j)*2+1], vf, sy);
    cnt = __fadd_rn(cnt, vf);
  }
  float dv = fmaxf(cnt, 1.0f);
  float mx = __fdiv_rn(sx, dv), my = __fdiv_rn(sy, dv);
  float ddx = __fsub_rn(fx, mx), ddy = __fsub_rn(fy, my);
  float dev = sqrtf(__fadd_rn(__fmaf_rn(ddy, ddy, __fmul_rn(ddx, ddx)), EPSF));
  int mi = g_maskA[row];
  bool keep = mi && ((cnt > 0.0f) ? (dev <= 2.0f) : true);
  g_idx1[row] = keep ? (g_idxA[row] + 1) : 0;
}

__global__ void k_dedup(){
  __shared__ int cnt[N_+1];
  int b = blockIdx.x, tid = threadIdx.x;
  for (int s = tid; s < N_+1; s += 1024) cnt[s] = 0;
  __syncthreads();
  int v0 = g_idx1[b*N_ + tid], v1 = g_idx1[b*N_ + tid + 1024];
  atomicAdd(&cnt[v0], 1); atomicAdd(&cnt[v1], 1);
  __syncthreads();
  if (cnt[v0] > 1) g_idx1[b*N_ + tid] = 0;
  if (cnt[v1] > 1) g_idx1[b*N_ + tid + 1024] = 0;
}

__global__ void k_finish(const float* __restrict__ xy1, const float* __restrict__ xy2,
                         float* __restrict__ outp, int withmask){
  int row = blockIdx.x*blockDim.x + threadIdx.x;
  if (row >= BN) return;
  int b = row / N_;
  int v = g_idx1[row];
  int mm = (v != 0);
  int j = (v - 1) * mm;
  float mf = (float)mm;
  float fx = __fmul_rn(__fsub_rn(xy2[(b*N_+j)*2],   xy1[row*2]),   mf);
  float fy = __fmul_rn(__fsub_rn(xy2[(b*N_+j)*2+1], xy1[row*2+1]), mf);
  g_flow[row*2] = fx; g_flow[row*2+1] = fy;
  g_mask[row] = mm;
  if (outp){
    outp[row*2] = fx; outp[row*2+1] = fy;
    if (withmask) outp[2*BN + row] = mf;
  }
}

// ---------------- masked grid KNN(4) + IDW interpolation ----------
__global__ void k_ggriddata(){
  int row = blockIdx.x*blockDim.x + threadIdx.x;
  if (row >= BN) return;
  int b = row / N_;
  float4 q = g_xy1p[row];
  unsigned long long out[4];
  grid_knn<4,true,false,false>(b, -1, q.x, q.y, g_gp1, g_cs1, g_pl1, g_xy1p, g_mask, out);

  float ws = 0.f, sx = 0.f, sy = 0.f;
  #pragma unroll
  for (int s=0; s<4; s++){
    float d = __uint_as_float((unsigned)(out[s] >> 32));
    float vf = (d < 5e8f) ? 1.0f : 0.0f;
    int j = (d < 5e8f) ? (int)(out[s] & 0xFFFFFFFFu) : 0;
    float w = __fdiv_rn(vf, __fadd_rn(d, 1e-6f));
    sx = __fmaf_rn(w, g_flow[(b*N_+j)*2],   sx);
    sy = __fmaf_rn(w, g_flow[(b*N_+j)*2+1], sy);
    ws = __fadd_rn(ws, w);
  }
  float ix = __fdiv_rn(sx, __fadd_rn(ws, EPSF));
  float iy = __fdiv_rn(sy, __fadd_rn(ws, EPSF));
  int m = g_mask[row];
  g_fgri[row*2]   = m ? g_flow[row*2]   : ix;
  g_fgri[row*2+1] = m ? g_flow[row*2+1] : iy;
}

// ---------------- host orchestration ----------------
extern "C" void kernel_launch(void* const* d_in, const int* in_sizes, int n_in,
                              void* d_out, int out_size){
  const float* xy1 = (const float*)d_in[0];
  const float* xy2 = (const float*)d_in[1];
  const float* f1  = (const float*)d_in[2];
  const float* f2  = (const float*)d_in[3];
  const float* gam = (const float*)d_in[4];
  const float* eps = (const float*)d_in[5];
  float* outp = (float*)d_out;
  int withmask = (out_size >= BN*3) ? 1 : 0;

  float4 *p_xy1p, *p_xy2p, *p_xy11p, *p_gp1, *p_gp2, *p_gp11;
  float *p_rowD;
  int *p_nbA, *p_nbB, *p_cand, *p_rowIdx, *p_colArg;
  int *p_cs1, *p_cs2, *p_cs11, *p_pl1, *p_pl2, *p_pl11;
  cudaGetSymbolAddress((void**)&p_xy1p,   g_xy1p);
  cudaGetSymbolAddress((void**)&p_xy2p,   g_xy2p);
  cudaGetSymbolAddress((void**)&p_xy11p,  g_xy11p);
  cudaGetSymbolAddress((void**)&p_gp1,    g_gp1);
  cudaGetSymbolAddress((void**)&p_gp2,    g_gp2);
  cudaGetSymbolAddress((void**)&p_gp11,   g_gp11);
  cudaGetSymbolAddress((void**)&p_cs1,    g_cs1);
  cudaGetSymbolAddress((void**)&p_cs2,    g_cs2);
  cudaGetSymbolAddress((void**)&p_cs11,   g_cs11);
  cudaGetSymbolAddress((void**)&p_pl1,    g_pl1);
  cudaGetSymbolAddress((void**)&p_pl2,    g_pl2);
  cudaGetSymbolAddress((void**)&p_pl11,   g_pl11);
  cudaGetSymbolAddress((void**)&p_nbA,    g_nbA);
  cudaGetSymbolAddress((void**)&p_nbB,    g_nbB);
  cudaGetSymbolAddress((void**)&p_cand,   g_cand);
  cudaGetSymbolAddress((void**)&p_rowD,   g_rowD);
  cudaGetSymbolAddress((void**)&p_rowIdx, g_rowIdx);
  cudaGetSymbolAddress((void**)&p_colArg, g_colArg);

  const int QB = 64, QG = BN/QB;   // thread-per-row grid-query launches
  const int TB = 256, GT = (BN+TB-1)/TB;

  k_params<<<1,1>>>(gam, eps);
  k_norms<<<(2*BN*32)/256, 256>>>(f1, f2);
  k_normalize<<<(2*BN*C_ + 255)/256, 256>>>(f1, f2);
  k_prep<<<GT, TB>>>(xy1, p_xy1p, 0);
  k_prep<<<GT, TB>>>(xy2, p_xy2p, 0);
  k_gridbuild<<<B_, 1024>>>(p_xy1p, p_gp1, p_cs1, p_pl1);
  k_gridbuild<<<B_, 1024>>>(p_xy2p, p_gp2, p_cs2, p_pl2);
  k_gknn<12,false><<<QG, QB>>>(p_xy1p, p_gp1, p_cs1, p_pl1, p_xy1p, p_nbA, nullptr);
  k_gknn<12,false><<<QG, QB>>>(p_xy2p, p_gp2, p_cs2, p_pl2, p_xy2p, p_nbB, nullptr);

  // ---- two sinkhorn matching passes ----
  for (int pass = 0; pass < 2; pass++){
    const float4* qp = p_xy1p;
    if (pass){ k_prep<<<GT, TB>>>(xy1, p_xy11p, 1); qp = p_xy11p; }
    k_gknn<4,false><<<QG, QB>>>(qp, p_gp2, p_cs2, p_pl2, p_xy2p, p_cand, nullptr);
    k_kc<<<(BN*4+127)/128, 128>>>();
    k_ctbuild<<<B_, 1024>>>();
    for (int r = 0; r < 4; r++){
      k_sinkhorn<<<2, 1024>>>(r + 1);
      if (r == 0) k_simmerge<8,0><<<GT, TB>>>(xy1, xy2);
      else        k_simmerge<8,1><<<GT, TB>>>(xy1, xy2);
      k_goutlier<<<QG, QB>>>();
      if (r > 0) k_dedup<<<2, 1024>>>();
    }
    k_finish<<<GT, TB>>>(xy1, xy2, nullptr, 0);
    k_ggriddata<<<QG, QB>>>();
  }

  // ---- two KNN matching passes ----
  for (int pass = 0; pass < 2; pass++){
    int final = (pass == 1);
    k_prep<<<GT, TB>>>(xy1, p_xy11p, 1);
    k_gridbuild<<<B_, 1024>>>(p_xy11p, p_gp11, p_cs11, p_pl11);
    k_gknn<2,true><<<QG, QB>>>(p_xy11p, p_gp2, p_cs2, p_pl2, p_xy2p, p_rowIdx, p_rowD);
    k_gknn<1,true><<<QG, QB>>>(p_xy2p, p_gp11, p_cs11, p_pl11, p_xy11p, p_colArg, nullptr);
    k_simmerge<11,2><<<GT, TB>>>(xy1, xy2);
    k_goutlier<<<QG, QB>>>();
    k_finish<<<GT, TB>>>(xy1, xy2, final ? outp : nullptr, withmask);
    if (!final) k_ggriddata<<<QG, QB>>>();
  }
}

// round 8
// speedup vs baseline: 1.9798x; 1.8562x over previous
#include <cuda_runtime.h>
#include <stdint.h>
#include <math.h>

#define N_   2048
#define B_   2
#define C_   512
#define BN   (B_*N_)
#define EPSF 1e-8f
#define BIGF 1e9f
#define WPB  8          // warps per scan block
#define SCAP 128        // per-warp accept buffer capacity

// ---------------- device scratch ----------------
__device__ float  g_nrm1[BN], g_nrm2[BN];
__device__ float  g_f1n[BN*C_], g_f2n[BN*C_];
__device__ float4 g_xy1p[BN], g_xy2p[BN], g_xy11p[BN];   // (x, y, rb, 0)
__device__ int    g_nbA[BN*12], g_nbB[BN*12];
__device__ int    g_cand[BN*4];
__device__ float  g_Kc[BN*4];
__device__ int    g_sord[BN];
__device__ int    g_ccnt[B_*N_], g_coff[B_*N_];
__device__ int    g_tlist[B_*N_*4];
__device__ int    g_idx0[BN], g_idxA[BN], g_maskA[BN], g_idx1[BN], g_mask[BN];
__device__ unsigned g_bitsA[B_*(N_/32)], g_bitsM[B_*(N_/32)];
__device__ float  g_flow[BN*2], g_fgri[BN*2];
__device__ float  g_rowD[BN*2];
__device__ int    g_rowIdx[BN*2];
__device__ int    g_colArg[BN];
__device__ float  g_par[2];   // [0]=eps, [1]=power

__global__ void k_params(const float* gam, const float* eps){
  float e = __fadd_rn(expf(eps[0]), 0.03f);
  float g = expf(gam[0]);
  g_par[0] = e;
  g_par[1] = __fdiv_rn(g, __fadd_rn(g, e));
}

__global__ void k_norms(const float* __restrict__ f1, const float* __restrict__ f2){
  int w = (blockIdx.x*blockDim.x + threadIdx.x) >> 5;
  int lane = threadIdx.x & 31;
  if (w >= 2*BN) return;
  const float* f = (w < BN) ? (f1 + (size_t)w*C_) : (f2 + (size_t)(w-BN)*C_);
  float s = 0.f;
  for (int c = lane; c < C_; c += 32) s = __fmaf_rn(f[c], f[c], s);
  #pragma unroll
  for (int off=16; off; off>>=1) s = __fadd_rn(s, __shfl_xor_sync(0xffffffffu, s, off));
  if (lane == 0){
    float n = __fadd_rn(sqrtf(s), EPSF);
    if (w < BN) g_nrm1[w] = n; else g_nrm2[w-BN] = n;
  }
}

__global__ void k_normalize(const float* __restrict__ f1, const float* __restrict__ f2){
  int e = blockIdx.x*blockDim.x + threadIdx.x;
  const int tot = BN*C_;
  if (e < tot){
    g_f1n[e] = __fdiv_rn(f1[e], g_nrm1[e / C_]);
  } else if (e < 2*tot){
    int e2 = e - tot;
    g_f2n[e2] = __fdiv_rn(f2[e2], g_nrm2[e2 / C_]);
  }
}

__global__ void k_prep(const float* __restrict__ xy, float4* __restrict__ dst, int addflow){
  int p = blockIdx.x*blockDim.x + threadIdx.x;
  if (p >= BN) return;
  float x = xy[p*2], y = xy[p*2+1];
  if (addflow){ x = __fadd_rn(x, g_fgri[p*2]); y = __fadd_rn(y, g_fgri[p*2+1]); }
  dst[p] = make_float4(x, y, __fmaf_rn(y, y, __fmul_rn(x, x)), 0.f);
}

// ---------------- fallback: insertion-sort warp top-K (rare; bit-identical) --------
template<int K, bool MASKC, bool EYE, bool SQRT>
__device__ __noinline__ void warp_topk_ins(
    const float4* __restrict__ Q, const float4* __restrict__ R,
    const unsigned* __restrict__ mbits, int row, unsigned long long (&out)[K])
{
  const unsigned FULL = 0xffffffffu;
  int lane = threadIdx.x & 31;
  int b = row >> 11, i = row & (N_-1);
  float4 q = __ldg(&Q[row]);
  const float4* Rb = R + (size_t)b*N_;
  unsigned w0 = FULL, w1 = FULL;
  if (MASKC){
    const unsigned* mb = mbits + b*(N_/32);
    w0 = __ldg(&mb[lane]); w1 = __ldg(&mb[32+lane]);
  }
  unsigned long long best[K];
  #pragma unroll
  for (int s=0; s<K; s++) best[s] = 0x7F800000FFFFFFFFull;
  float dlast = __uint_as_float(0x7F800000u);
  float U     = __uint_as_float(0x7FC00000u);

  for (int t=0; t<64; t++){
    int j = lane + 32*t;
    float4 r = __ldg(&Rb[j]);
    float dt = __fmaf_rn(q.y, r.y, __fmul_rn(q.x, r.x));
    float d  = fmaxf(__fsub_rn(__fadd_rn(q.z, r.z), __fmul_rn(2.0f, dt)), 0.0f);
    if (MASKC){
      unsigned wv = __shfl_sync(FULL, (t<32)?w0:w1, t&31);
      if (!((wv>>lane)&1u)) d = BIGF;
    }
    if (EYE){ if (j == i) d = __fadd_rn(d, BIGF); }
    bool try_ins;
    if (SQRT){
      float d2pe = __fadd_rn(d, EPSF);
      try_ins = !(d2pe > U);
      if (try_ins) d = sqrtf(d2pe);
    } else try_ins = (d <= dlast);
    if (try_ins){
      unsigned long long key = ((unsigned long long)__float_as_uint(d) << 32) | (unsigned)j;
      if (key < best[K-1]){
        best[K-1] = key;
        #pragma unroll
        for (int s=K-1; s>0; s--){
          if (best[s] < best[s-1]){
            unsigned long long tmp = best[s-1]; best[s-1] = best[s]; best[s] = tmp;
          } else break;
        }
        unsigned hb = (unsigned)(best[K-1] >> 32);
        if (SQRT){
          float up = __uint_as_float(hb + 1);
          U = __fmul_ru(up, up);
        } else dlast = __uint_as_float(hb);
      }
    }
  }
  #pragma unroll
  for (int s=0; s<K; s++){
    unsigned long long c = best[0];
    unsigned long long m = c;
    #pragma unroll
    for (int off=16; off; off>>=1){
      unsigned long long o = __shfl_xor_sync(FULL, m, off);
      m = (o < m) ? o : m;
    }
    if (c == m){
      #pragma unroll
      for (int u=0; u<K-1; u++) best[u] = best[u+1];
      best[K-1] = 0x7F800000FFFFFFFFull;
    }
    out[s] = m;
  }
}

// ---------------- two-phase divergence-free exact warp top-K ----------------
template<int K, bool MASKC, bool EYE, bool SQRT>
__device__ __forceinline__ void warp_topk2(
    const float4* __restrict__ Q, const float4* __restrict__ R,
    const unsigned* __restrict__ mbits, int row,
    unsigned long long* __restrict__ sbuf, unsigned long long (&out)[K])
{
  const unsigned FULL = 0xffffffffu;
  const unsigned long long INFK = 0x7F800000FFFFFFFFull;
  int lane = threadIdx.x & 31;
  int b = row >> 11, i = row & (N_-1);
  float4 q = __ldg(&Q[row]);
  const float4* Rb = R + (size_t)b*N_;
  unsigned w0 = FULL, w1 = FULL;
  if (MASKC){
    const unsigned* mb = mbits + b*(N_/32);
    w0 = __ldg(&mb[lane]); w1 = __ldg(&mb[32+lane]);
  }

  // phase 1: per-lane min of modified d2 (branchless)
  float mn = __uint_as_float(0x7F800000u);
  #pragma unroll 4
  for (int t=0; t<64; t++){
    int j = lane + 32*t;
    float4 r = __ldg(&Rb[j]);
    float dt = __fmaf_rn(q.y, r.y, __fmul_rn(q.x, r.x));
    float d  = fmaxf(__fsub_rn(__fadd_rn(q.z, r.z), __fmul_rn(2.0f, dt)), 0.0f);
    if (MASKC){
      unsigned wv = __shfl_sync(FULL, (t<32)?w0:w1, t&31);
      if (!((wv>>lane)&1u)) d = BIGF;
    }
    if (EYE){ if (j == i) d = __fadd_rn(d, BIGF); }
    mn = fminf(mn, d);
  }
  // tau = K-th smallest of the 32 lane minima (upper bound on true K-th distance)
  float v = mn, tau = 0.f;
  #pragma unroll
  for (int s=0; s<K; s++){
    float g = v;
    #pragma unroll
    for (int off=16; off; off>>=1) g = fminf(g, __shfl_xor_sync(FULL, g, off));
    tau = g;
    unsigned hit = __ballot_sync(FULL, v == g);
    if (lane == (__ffs(hit)-1)) v = __uint_as_float(0x7F800000u);
  }
  float ub = 0.f;
  if (SQRT){
    float S  = sqrtf(__fadd_rn(tau, EPSF));
    float su = __uint_as_float(__float_as_uint(S) + 1);   // nextup(S)
    ub = __fmul_ru(su, su);                               // conservative d2+eps bound
  }

  // phase 2: rescan, ballot-compact accepted into per-warp shared buffer
  int cnt = 0;
  #pragma unroll 4
  for (int t=0; t<64; t++){
    int j = lane + 32*t;
    float4 r = __ldg(&Rb[j]);
    float dt = __fmaf_rn(q.y, r.y, __fmul_rn(q.x, r.x));
    float d  = fmaxf(__fsub_rn(__fadd_rn(q.z, r.z), __fmul_rn(2.0f, dt)), 0.0f);
    if (MASKC){
      unsigned wv = __shfl_sync(FULL, (t<32)?w0:w1, t&31);
      if (!((wv>>lane)&1u)) d = BIGF;
    }
    if (EYE){ if (j == i) d = __fadd_rn(d, BIGF); }
    bool acc;
    if (SQRT) acc = (__fadd_rn(d, EPSF) < ub);
    else      acc = (d <= tau);
    unsigned bal = __ballot_sync(FULL, acc);
    if (acc){
      int pos = cnt + __popc(bal & ((1u<<lane)-1u));
      if (pos < SCAP){
        float kd = SQRT ? sqrtf(__fadd_rn(d, EPSF)) : d;
        sbuf[pos] = ((unsigned long long)__float_as_uint(kd) << 32) | (unsigned)j;
      }
    }
    cnt += __popc(bal);
  }
  if (cnt > SCAP){
    warp_topk_ins<K,MASKC,EYE,SQRT>(Q, R, mbits, row, out);
    return;
  }
  __syncwarp();
  // phase 3: exact K-round extraction over <=SCAP unique keys
  unsigned long long mk[SCAP/32];
  #pragma unroll
  for (int u=0; u<SCAP/32; u++){
    int idx = lane + 32*u;
    mk[u] = (idx < cnt) ? sbuf[idx] : INFK;
  }
  #pragma unroll
  for (int s=0; s<K; s++){
    unsigned long long lm = mk[0]; int slot = 0;
    #pragma unroll
    for (int u=1; u<SCAP/32; u++) if (mk[u] < lm){ lm = mk[u]; slot = u; }
    unsigned long long g = lm;
    #pragma unroll
    for (int off=16; off; off>>=1){
      unsigned long long o = __shfl_xor_sync(FULL, g, off);
      g = (o < g) ? o : g;
    }
    out[s] = g;
    if (lm == g){
      #pragma unroll
      for (int u=0; u<SCAP/32; u++) if (u == slot) mk[u] = INFK;
    }
  }
}

template<int K, bool SQRT>
__global__ void k_knn_write(const float4* __restrict__ Q, const float4* __restrict__ R,
                            int* __restrict__ oIdx, float* __restrict__ oD){
  __shared__ unsigned long long sb[WPB*SCAP];
  int w = threadIdx.x >> 5;
  int row = blockIdx.x*WPB + w;
  if (row >= BN) return;
  unsigned long long out[K];
  warp_topk2<K,false,false,SQRT>(Q, R, nullptr, row, sb + w*SCAP, out);
  if ((threadIdx.x & 31) == 0){
    #pragma unroll
    for (int s=0; s<K; s++){
      oIdx[row*K+s] = (int)(out[s] & 0xFFFFFFFFu);
      if (oD) oD[row*K+s] = __uint_as_float((unsigned)(out[s] >> 32));
    }
  }
}

// ---------------- feature-cost ----------
__global__ void k_kc(){
  int e = blockIdx.x*blockDim.x + threadIdx.x;
  if (e >= BN*4) return;
  int w = e >> 2, c = e & 3;
  int b = w / N_;
  int j = g_cand[w*4+c];
  const float4* f1 = (const float4*)(g_f1n + (size_t)w*C_);
  const float4* f2 = (const float4*)(g_f2n + ((size_t)(b*N_ + j))*C_);
  float s = 0.f;
  #pragma unroll 4
  for (int k=0; k<C_/4; k++){
    float4 A = f1[k], Bv = __ldg(&f2[k]);
    s = __fmaf_rn(A.x, Bv.x, s);
    s = __fmaf_rn(A.y, Bv.y, s);
    s = __fmaf_rn(A.z, Bv.z, s);
    s = __fmaf_rn(A.w, Bv.w, s);
  }
  float Cmv = __fsub_rn(1.0f, s);
  g_Kc[w*4+c] = expf(__fdiv_rn(-Cmv, g_par[0]));
  if (c == 0){
    int k0 = (g_cand[w*4+0]<<2)|0, k1 = (g_cand[w*4+1]<<2)|1;
    int k2 = (g_cand[w*4+2]<<2)|2, k3 = (g_cand[w*4+3]<<2)|3;
    int t;
    if (k0>k1){t=k0;k0=k1;k1=t;} if (k2>k3){t=k2;k2=k3;k3=t;}
    if (k0>k2){t=k0;k0=k2;k2=t;} if (k1>k3){t=k1;k1=k3;k3=t;}
    if (k1>k2){t=k1;k1=k2;k2=t;}
    g_sord[w] = (k0&3) | ((k1&3)<<2) | ((k2&3)<<4) | ((k3&3)<<6);
  }
}

// ---------------- transpose-list build (one block per batch) ----------------
__global__ void k_ctbuild(){
  __shared__ int scnt[N_];
  __shared__ int scur[N_];
  int b = blockIdx.x, tid = threadIdx.x;
  scnt[tid] = 0; scnt[tid+1024] = 0;
  __syncthreads();
  #pragma unroll
  for (int rr=0; rr<2; rr++){
    int i = tid + rr*1024;
    #pragma unroll
    for (int c=0; c<4; c++) atomicAdd(&scnt[g_cand[(b*N_+i)*4+c]], 1);
  }
  __syncthreads();
  if (tid < 32){
    int lo = tid*64, tot = 0;
    for (int t=0; t<64; t++) tot += scnt[lo+t];
    int inc = tot;
    #pragma unroll
    for (int off=1; off<32; off<<=1){
      int v = __shfl_up_sync(0xffffffffu, inc, off);
      if (tid >= off) inc += v;
    }
    int run = inc - tot;
    for (int t=0; t<64; t++){
      g_coff[b*N_+lo+t] = run;
      scur[lo+t] = run;
      g_ccnt[b*N_+lo+t] = scnt[lo+t];
      run += scnt[lo+t];
    }
  }
  __syncthreads();
  #pragma unroll
  for (int rr=0; rr<2; rr++){
    int i = tid + rr*1024;
    #pragma unroll
    for (int c=0; c<4; c++){
      int j = g_cand[(b*N_+i)*4+c];
      int pos = atomicAdd(&scur[j], 1);
      g_tlist[b*N_*4 + pos] = (i<<2) | c;
    }
  }
  __syncthreads();
  #pragma unroll
  for (int rr=0; rr<2; rr++){
    int col = tid + rr*1024;
    int off = g_coff[b*N_+col], cnt = g_ccnt[b*N_+col];
    int* L = g_tlist + b*N_*4 + off;
    for (int a2=1; a2<cnt; a2++){
      int v = L[a2]; int p = a2-1;
      while (p >= 0 && L[p] > v){ L[p+1] = L[p]; p--; }
      L[p+1] = v;
    }
  }
}

// ---------------- fused sparse sinkhorn (5 iters) + mutual-best recon ----------------
__global__ void k_sinkhorn(int dr0){
  __shared__ float su[N_], sv[N_];
  __shared__ unsigned long long ck[N_];
  int b = blockIdx.x, tid = threadIdx.x;
  const int* cb = g_cand + b*N_*4;
  const float* Kb = g_Kc + b*N_*4;
  const int* sob = g_sord + b*N_;
  const int* tl = g_tlist + b*N_*4;
  const float P = 1.0f/2048.0f;
  float pw = g_par[1];

  sv[tid] = 1.f; sv[tid+1024] = 1.f;
  __syncthreads();

  for (int t=0; t<5; t++){
    #pragma unroll
    for (int rr=0; rr<2; rr++){
      int i = tid + rr*1024;
      int o = sob[i];
      float s = 0.f;
      #pragma unroll
      for (int p=0; p<4; p++){
        int sl = (o >> (2*p)) & 3;
        if (sl < dr0)
          s = __fmaf_rn(Kb[i*4+sl], sv[cb[i*4+sl]], s);
      }
      su[i] = powf(__fdiv_rn(P, __fadd_rn(s, EPSF)), pw);
    }
    __syncthreads();
    #pragma unroll
    for (int rr=0; rr<2; rr++){
      int j = tid + rr*1024;
      int off = g_coff[b*N_+j], cnt = g_ccnt[b*N_+j];
      float s = 0.f;
      for (int p=0; p<cnt; p++){
        int e = tl[off+p];
        int c = e & 3;
        if (c < dr0){
          int i = e >> 2;
          s = __fmaf_rn(Kb[i*4+c], su[i], s);
        }
      }
      sv[j] = powf(__fdiv_rn(P, __fadd_rn(s, EPSF)), pw);
    }
    __syncthreads();
  }

  ck[tid] = 0xFFFFFFFFull; ck[tid+1024] = 0xFFFFFFFFull;
  __syncthreads();
  #pragma unroll
  for (int rr=0; rr<2; rr++){
    int i = tid + rr*1024;
    float ui = su[i];
    for (int c=0; c<dr0; c++){
      int j = cb[i*4+c];
      float tv = __fmul_rn(__fmul_rn(ui, Kb[i*4+c]), sv[j]);
      unsigned long long key = ((unsigned long long)__float_as_uint(tv) << 32)
                             | (unsigned)(~(unsigned)i);
      atomicMax(&ck[j], key);
    }
  }
  __syncthreads();
  #pragma unroll
  for (int rr=0; rr<2; rr++){
    int i = tid + rr*1024;
    float ui = su[i];
    unsigned long long k0 = 0ull, k1 = 0ull;
    for (int c=0; c<dr0; c++){
      int j = cb[i*4+c];
      float tv = __fmul_rn(__fmul_rn(ui, Kb[i*4+c]), sv[j]);
      unsigned long long key = ((unsigned long long)__float_as_uint(tv) << 32)
                             | (unsigned)(~(unsigned)j);
      if (key > k0){ k1 = k0; k0 = key; }
      else if (key > k1){ k1 = key; }
    }
    float rv0 = __uint_as_float((unsigned)(k0 >> 32));
    float rv1 = __uint_as_float((unsigned)(k1 >> 32));
    int bj = (int)(~(unsigned)k0);
    int bi = (int)(~(unsigned)ck[bj]);
    bool ok = rv0 > __fmul_rn(1.2f, rv1);
    g_idx0[b*N_ + i] = (bi == i && ok) ? bj : -1;
  }
}

// ---------------- merge (+optional knn recon) + similarity verify + bitpack --------
template<int SIMK, int MODE>
__global__ void k_simmerge(const float* __restrict__ xy1, const float* __restrict__ xy2){
  int row = blockIdx.x*blockDim.x + threadIdx.x;
  int b = row / N_, i = row - b*N_;
  int m;
  if (MODE == 0) m = g_idx0[row];
  else if (MODE == 1){ int p = g_idx1[row]; m = (p == 0) ? g_idx0[row] : (p - 1); }
  else {
    float d0 = g_rowD[row*2], d1 = g_rowD[row*2+1];
    int bj = g_rowIdx[row*2];
    bool ok = __fmul_rn(d0, 1.2f) < d1;
    bool mut = (g_colArg[b*N_ + bj] == i);
    m = (ok && mut) ? bj : -1;
  }

  int outv = -1;
  if (m >= 0){
    const float* X1 = xy1 + (size_t)b*N_*2;
    const float* X2 = xy2 + (size_t)b*N_*2;
    float pix = X1[i*2], piy = X1[i*2+1];
    float pjx = X2[m*2], pjy = X2[m*2+1];
    float o1x[SIMK], o1y[SIMK], o2x[SIMK], o2y[SIMK];
    #pragma unroll
    for (int k=0; k<SIMK; k++){
      int a = g_nbA[row*12 + 1 + k];
      o1x[k] = __fsub_rn(X1[a*2],   pix);
      o1y[k] = __fsub_rn(X1[a*2+1], piy);
      int c = g_nbB[(b*N_+m)*12 + 1 + k];
      o2x[k] = __fsub_rn(X2[c*2],   pjx);
      o2y[k] = __fsub_rn(X2[c*2+1], pjy);
    }
    float colmin[SIMK];
    #pragma unroll
    for (int l=0; l<SIMK; l++) colmin[l] = 3.4e38f;
    float sum1 = 0.f;
    #pragma unroll
    for (int k=0; k<SIMK; k++){
      float rmn = 3.4e38f;
      #pragma unroll
      for (int l=0; l<SIMK; l++){
        float dx = __fsub_rn(o1x[k], o2x[l]);
        float dy = __fsub_rn(o1y[k], o2y[l]);
        float d = sqrtf(__fadd_rn(__fmaf_rn(dy, dy, __fmul_rn(dx, dx)), EPSF));
        rmn = fminf(rmn, d);
        colmin[l] = fminf(colmin[l], d);
      }
      sum1 = __fadd_rn(sum1, rmn);
    }
    float sum2 = 0.f;
    #pragma unroll
    for (int l=0; l<SIMK; l++) sum2 = __fadd_rn(sum2, colmin[l]);
    float Kf = (float)SIMK;
    float cham = __fmul_rn(0.5f, __fadd_rn(__fdiv_rn(sum1, Kf), __fdiv_rn(sum2, Kf)));
    if (cham <= 2.0f) outv = m;
  }
  g_idxA[row] = outv;
  int mm = (outv >= 0);
  g_maskA[row] = mm;
  int j = (outv >= 0) ? outv : 0;
  float mf = (float)mm;
  g_flow[row*2]   = __fmul_rn(__fsub_rn(xy2[(b*N_+j)*2],   xy1[row*2]),   mf);
  g_flow[row*2+1] = __fmul_rn(__fsub_rn(xy2[(b*N_+j)*2+1], xy1[row*2+1]), mf);
  unsigned bal = __ballot_sync(0xffffffffu, mm);
  if ((threadIdx.x & 31) == 0) g_bitsA[row >> 5] = bal;
}

// ---------------- masked topk(8)+eye + outlier rejection ----------
__global__ void k_outlier(){
  __shared__ unsigned long long sb[WPB*SCAP];
  int w = threadIdx.x >> 5;
  int row = blockIdx.x*WPB + w;
  if (row >= BN) return;
  unsigned long long out[8];
  warp_topk2<8,true,true,false>(g_xy1p, g_xy1p, g_bitsA, row, sb + w*SCAP, out);
  if ((threadIdx.x & 31) == 0){
    int b = row / N_;
    float fx = g_flow[row*2], fy = g_flow[row*2+1];
    float sx = 0.f, sy = 0.f, cnt = 0.f;
    #pragma unroll
    for (int s=0; s<8; s++){
      float d = __uint_as_float((unsigned)(out[s] >> 32));
      float vf = (d < 5e8f) ? 1.0f : 0.0f;
      int j = (d < 5e8f) ? (int)(out[s] & 0xFFFFFFFFu) : 0;
      sx = __fmaf_rn(g_flow[(b*N_+j)*2],   vf, sx);
      sy = __fmaf_rn(g_flow[(b*N_+j)*2+1], vf, sy);
      cnt = __fadd_rn(cnt, vf);
    }
    float dv = fmaxf(cnt, 1.0f);
    float mx = __fdiv_rn(sx, dv), my = __fdiv_rn(sy, dv);
    float ddx = __fsub_rn(fx, mx), ddy = __fsub_rn(fy, my);
    float dev = sqrtf(__fadd_rn(__fmaf_rn(ddy, ddy, __fmul_rn(ddx, ddx)), EPSF));
    int mi = g_maskA[row];
    bool keep = mi && ((cnt > 0.0f) ? (dev <= 2.0f) : true);
    g_idx1[row] = keep ? (g_idxA[row] + 1) : 0;
  }
}

__global__ void k_dedup(){
  __shared__ int cnt[N_+1];
  int b = blockIdx.x, tid = threadIdx.x;
  for (int s = tid; s < N_+1; s += 1024) cnt[s] = 0;
  __syncthreads();
  int v0 = g_idx1[b*N_ + tid], v1 = g_idx1[b*N_ + tid + 1024];
  atomicAdd(&cnt[v0], 1); atomicAdd(&cnt[v1], 1);
  __syncthreads();
  if (cnt[v0] > 1) g_idx1[b*N_ + tid] = 0;
  if (cnt[v1] > 1) g_idx1[b*N_ + tid + 1024] = 0;
}

__global__ void k_finish(const float* __restrict__ xy1, const float* __restrict__ xy2,
                         float* __restrict__ outp, int withmask){
  int row = blockIdx.x*blockDim.x + threadIdx.x;
  int b = row / N_;
  int v = g_idx1[row];
  int mm = (v != 0);
  int j = (v - 1) * mm;
  float mf = (float)mm;
  float fx = __fmul_rn(__fsub_rn(xy2[(b*N_+j)*2],   xy1[row*2]),   mf);
  float fy = __fmul_rn(__fsub_rn(xy2[(b*N_+j)*2+1], xy1[row*2+1]), mf);
  g_flow[row*2] = fx; g_flow[row*2+1] = fy;
  g_mask[row] = mm;
  if (outp){
    outp[row*2] = fx; outp[row*2+1] = fy;
    if (withmask) outp[2*BN + row] = mf;
  }
  unsigned bal = __ballot_sync(0xffffffffu, mm);
  if ((threadIdx.x & 31) == 0) g_bitsM[row >> 5] = bal;
}

// ---------------- masked topk(4) + IDW interpolation ----------
__global__ void k_griddata(){
  __shared__ unsigned long long sb[WPB*SCAP];
  int w = threadIdx.x >> 5;
  int row = blockIdx.x*WPB + w;
  if (row >= BN) return;
  unsigned long long out[4];
  warp_topk2<4,true,false,false>(g_xy1p, g_xy1p, g_bitsM, row, sb + w*SCAP, out);
  if ((threadIdx.x & 31) == 0){
    int b = row / N_;
    float ws = 0.f, sx = 0.f, sy = 0.f;
    #pragma unroll
    for (int s=0; s<4; s++){
      float d = __uint_as_float((unsigned)(out[s] >> 32));
      float vf = (d < 5e8f) ? 1.0f : 0.0f;
      int j = (d < 5e8f) ? (int)(out[s] & 0xFFFFFFFFu) : 0;
      float wt = __fdiv_rn(vf, __fadd_rn(d, 1e-6f));
      sx = __fmaf_rn(wt, g_flow[(b*N_+j)*2],   sx);
      sy = __fmaf_rn(wt, g_flow[(b*N_+j)*2+1], sy);
      ws = __fadd_rn(ws, wt);
    }
    float ix = __fdiv_rn(sx, __fadd_rn(ws, EPSF));
    float iy = __fdiv_rn(sy, __fadd_rn(ws, EPSF));
    int m = g_mask[row];
    g_fgri[row*2]   = m ? g_flow[row*2]   : ix;
    g_fgri[row*2+1] = m ? g_flow[row*2+1] : iy;
  }
}

// ---------------- host orchestration ----------------
extern "C" void kernel_launch(void* const* d_in, const int* in_sizes, int n_in,
                              void* d_out, int out_size){
  const float* xy1 = (const float*)d_in[0];
  const float* xy2 = (const float*)d_in[1];
  const float* f1  = (const float*)d_in[2];
  const float* f2  = (const float*)d_in[3];
  const float* gam = (const float*)d_in[4];
  const float* eps = (const float*)d_in[5];
  float* outp = (float*)d_out;
  int withmask = (out_size >= BN*3) ? 1 : 0;

  float4 *p_xy1p, *p_xy2p, *p_xy11p;
  float *p_rowD;
  int *p_nbA, *p_nbB, *p_cand, *p_rowIdx, *p_colArg;
  cudaGetSymbolAddress((void**)&p_xy1p,   g_xy1p);
  cudaGetSymbolAddress((void**)&p_xy2p,   g_xy2p);
  cudaGetSymbolAddress((void**)&p_xy11p,  g_xy11p);
  cudaGetSymbolAddress((void**)&p_nbA,    g_nbA);
  cudaGetSymbolAddress((void**)&p_nbB,    g_nbB);
  cudaGetSymbolAddress((void**)&p_cand,   g_cand);
  cudaGetSymbolAddress((void**)&p_rowD,   g_rowD);
  cudaGetSymbolAddress((void**)&p_rowIdx, g_rowIdx);
  cudaGetSymbolAddress((void**)&p_colArg, g_colArg);

  const int WB = WPB*32;          // 256 threads
  const int GW = BN/WPB;          // 512 blocks
  const int TB = 256, GT = BN/TB;

  k_params<<<1,1>>>(gam, eps);
  k_norms<<<(2*BN*32)/256, 256>>>(f1, f2);
  k_normalize<<<(2*BN*C_ + 255)/256, 256>>>(f1, f2);
  k_prep<<<GT, TB>>>(xy1, p_xy1p, 0);
  k_prep<<<GT, TB>>>(xy2, p_xy2p, 0);
  k_knn_write<12,false><<<GW, WB>>>(p_xy1p, p_xy1p, p_nbA, nullptr);
  k_knn_write<12,false><<<GW, WB>>>(p_xy2p, p_xy2p, p_nbB, nullptr);

  // ---- two sinkhorn matching passes ----
  for (int pass = 0; pass < 2; pass++){
    const float4* qp = p_xy1p;
    if (pass){ k_prep<<<GT, TB>>>(xy1, p_xy11p, 1); qp = p_xy11p; }
    k_knn_write<4,false><<<GW, WB>>>(qp, p_xy2p, p_cand, nullptr);
    k_kc<<<(BN*4+127)/128, 128>>>();
    k_ctbuild<<<B_, 1024>>>();
    for (int r = 0; r < 4; r++){
      k_sinkhorn<<<2, 1024>>>(r + 1);
      if (r == 0) k_simmerge<8,0><<<GT, TB>>>(xy1, xy2);
      else        k_simmerge<8,1><<<GT, TB>>>(xy1, xy2);
      k_outlier<<<GW, WB>>>();
      if (r > 0) k_dedup<<<2, 1024>>>();
    }
    k_finish<<<GT, TB>>>(xy1, xy2, nullptr, 0);
    k_griddata<<<GW, WB>>>();
  }

  // ---- two KNN matching passes ----
  for (int pass = 0; pass < 2; pass++){
    int final = (pass == 1);
    k_prep<<<GT, TB>>>(xy1, p_xy11p, 1);
    k_knn_write<2,true><<<GW, WB>>>(p_xy11p, p_xy2p, p_rowIdx, p_rowD);   // row top-2 (D)
    k_knn_write<1,true><<<GW, WB>>>(p_xy2p, p_xy11p, p_colArg, nullptr);  // col argmin (D)
    k_simmerge<11,2><<<GT, TB>>>(xy1, xy2);
    k_outlier<<<GW, WB>>>();
    k_finish<<<GT, TB>>>(xy1, xy2, final ? outp : nullptr, withmask);
    if (!final) k_griddata<<<GW, WB>>>();
  }
}

// round 9
// speedup vs baseline: 2.8634x; 1.4463x over previous
#include <cuda_runtime.h>
#include <stdint.h>
#include <math.h>

#define N_   2048
#define B_   2
#define C_   512
#define BN   (B_*N_)
#define EPSF 1e-8f
#define BIGF 1e9f
#define WPB  8          // warps per scan block
#define SCAP 128        // per-warp accept buffer capacity

// ---------------- device scratch ----------------
__device__ float  g_f1n[BN*C_], g_f2n[BN*C_];
__device__ float4 g_xy1p[BN], g_xy2p[BN], g_xy11p[BN];   // (x, y, rb, 0)
__device__ int    g_nbA[BN*12], g_nbB[BN*12];
__device__ int    g_cand[BN*4];
__device__ float  g_Kc[BN*4];
__device__ int    g_sord[BN];
__device__ int    g_idx0R[4*BN];
__device__ int    g_idxA[BN], g_maskA[BN], g_idx1[BN], g_mask[BN];
__device__ unsigned g_bitsA[B_*(N_/32)], g_bitsM[B_*(N_/32)];
__device__ float  g_flow[BN*2];
__device__ float  g_rowD[BN*2];
__device__ int    g_rowIdx[BN*2];
__device__ int    g_colArg[BN];
__device__ float  g_par[2];   // [0]=eps, [1]=power

// ---------------- init: params + feature norms + normalize (fused) ----------------
__global__ void k_init(const float* __restrict__ f1, const float* __restrict__ f2,
                       const float* __restrict__ gam, const float* __restrict__ eps){
  int gw = (blockIdx.x*blockDim.x + threadIdx.x) >> 5;
  int lane = threadIdx.x & 31;
  if (gw == 0 && lane == 0){
    float e = __fadd_rn(expf(eps[0]), 0.03f);
    float g = expf(gam[0]);
    g_par[0] = e;
    g_par[1] = __fdiv_rn(g, __fadd_rn(g, e));
  }
  if (gw >= 2*BN) return;
  bool is1 = gw < BN;
  int row = is1 ? gw : gw - BN;
  const float* f = (is1 ? f1 : f2) + (size_t)row*C_;
  float*       o = (is1 ? g_f1n : g_f2n) + (size_t)row*C_;
  float v[16];
  float s = 0.f;
  #pragma unroll
  for (int t=0; t<16; t++){ v[t] = f[lane + 32*t]; s = __fmaf_rn(v[t], v[t], s); }
  #pragma unroll
  for (int off=16; off; off>>=1) s = __fadd_rn(s, __shfl_xor_sync(0xffffffffu, s, off));
  float n = __fadd_rn(sqrtf(s), EPSF);
  #pragma unroll
  for (int t=0; t<16; t++) o[lane + 32*t] = __fdiv_rn(v[t], n);
}

// prep both point arrays: (x, y, rb, 0), rb = fma(y,y, x*x)
__global__ void k_prep2(const float* __restrict__ xy1, const float* __restrict__ xy2){
  int p = blockIdx.x*blockDim.x + threadIdx.x;
  if (p >= 2*BN) return;
  bool is1 = p < BN;
  int row = is1 ? p : p - BN;
  const float* xy = is1 ? xy1 : xy2;
  float x = xy[row*2], y = xy[row*2+1];
  float4 v = make_float4(x, y, __fmaf_rn(y, y, __fmul_rn(x, x)), 0.f);
  if (is1) g_xy1p[row] = v; else g_xy2p[row] = v;
}

// ---------------- fallback: insertion-sort warp top-K (rare; bit-identical) --------
template<int K, bool MASKC, bool EYE, bool SQRT>
__device__ __noinline__ void warp_topk_ins(
    const float4* __restrict__ Q, const float4* __restrict__ R,
    const unsigned* __restrict__ mbits, int row, unsigned long long (&out)[K])
{
  const unsigned FULL = 0xffffffffu;
  int lane = threadIdx.x & 31;
  int b = row >> 11, i = row & (N_-1);
  float4 q = __ldg(&Q[row]);
  const float4* Rb = R + (size_t)b*N_;
  unsigned w0 = FULL, w1 = FULL;
  if (MASKC){
    const unsigned* mb = mbits + b*(N_/32);
    w0 = __ldg(&mb[lane]); w1 = __ldg(&mb[32+lane]);
  }
  unsigned long long best[K];
  #pragma unroll
  for (int s=0; s<K; s++) best[s] = 0x7F800000FFFFFFFFull;
  float dlast = __uint_as_float(0x7F800000u);
  float U     = __uint_as_float(0x7FC00000u);

  for (int t=0; t<64; t++){
    int j = lane + 32*t;
    float4 r = __ldg(&Rb[j]);
    float dt = __fmaf_rn(q.y, r.y, __fmul_rn(q.x, r.x));
    float d  = fmaxf(__fsub_rn(__fadd_rn(q.z, r.z), __fmul_rn(2.0f, dt)), 0.0f);
    if (MASKC){
      unsigned wv = __shfl_sync(FULL, (t<32)?w0:w1, t&31);
      if (!((wv>>lane)&1u)) d = BIGF;
    }
    if (EYE){ if (j == i) d = __fadd_rn(d, BIGF); }
    bool try_ins;
    if (SQRT){
      float d2pe = __fadd_rn(d, EPSF);
      try_ins = !(d2pe > U);
      if (try_ins) d = sqrtf(d2pe);
    } else try_ins = (d <= dlast);
    if (try_ins){
      unsigned long long key = ((unsigned long long)__float_as_uint(d) << 32) | (unsigned)j;
      if (key < best[K-1]){
        best[K-1] = key;
        #pragma unroll
        for (int s=K-1; s>0; s--){
          if (best[s] < best[s-1]){
            unsigned long long tmp = best[s-1]; best[s-1] = best[s]; best[s] = tmp;
          } else break;
        }
        unsigned hb = (unsigned)(best[K-1] >> 32);
        if (SQRT){
          float up = __uint_as_float(hb + 1);
          U = __fmul_ru(up, up);
        } else dlast = __uint_as_float(hb);
      }
    }
  }
  #pragma unroll
  for (int s=0; s<K; s++){
    unsigned long long c = best[0];
    unsigned long long m = c;
    #pragma unroll
    for (int off=16; off; off>>=1){
      unsigned long long o = __shfl_xor_sync(FULL, m, off);
      m = (o < m) ? o : m;
    }
    if (c == m){
      #pragma unroll
      for (int u=0; u<K-1; u++) best[u] = best[u+1];
      best[K-1] = 0x7F800000FFFFFFFFull;
    }
    out[s] = m;
  }
}

// ---------------- two-phase divergence-free exact warp top-K ----------------
template<int K, bool MASKC, bool EYE, bool SQRT>
__device__ __forceinline__ void warp_topk2(
    const float4* __restrict__ Q, const float4* __restrict__ R,
    const unsigned* __restrict__ mbits, int row,
    unsigned long long* __restrict__ sbuf, unsigned long long (&out)[K])
{
  const unsigned FULL = 0xffffffffu;
  const unsigned long long INFK = 0x7F800000FFFFFFFFull;
  int lane = threadIdx.x & 31;
  int b = row >> 11, i = row & (N_-1);
  float4 q = __ldg(&Q[row]);
  const float4* Rb = R + (size_t)b*N_;
  unsigned w0 = FULL, w1 = FULL;
  if (MASKC){
    const unsigned* mb = mbits + b*(N_/32);
    w0 = __ldg(&mb[lane]); w1 = __ldg(&mb[32+lane]);
  }

  // phase 1: per-lane min of modified d2 (branchless)
  float mn = __uint_as_float(0x7F800000u);
  #pragma unroll 4
  for (int t=0; t<64; t++){
    int j = lane + 32*t;
    float4 r = __ldg(&Rb[j]);
    float dt = __fmaf_rn(q.y, r.y, __fmul_rn(q.x, r.x));
    float d  = fmaxf(__fsub_rn(__fadd_rn(q.z, r.z), __fmul_rn(2.0f, dt)), 0.0f);
    if (MASKC){
      unsigned wv = __shfl_sync(FULL, (t<32)?w0:w1, t&31);
      if (!((wv>>lane)&1u)) d = BIGF;
    }
    if (EYE){ if (j == i) d = __fadd_rn(d, BIGF); }
    mn = fminf(mn, d);
  }
  // tau = K-th smallest of the 32 lane minima (upper bound on true K-th distance)
  float v = mn, tau = 0.f;
  #pragma unroll
  for (int s=0; s<K; s++){
    float g = v;
    #pragma unroll
    for (int off=16; off; off>>=1) g = fminf(g, __shfl_xor_sync(FULL, g, off));
    tau = g;
    unsigned hit = __ballot_sync(FULL, v == g);
    if (lane == (__ffs(hit)-1)) v = __uint_as_float(0x7F800000u);
  }
  float ub = 0.f;
  if (SQRT){
    float S  = sqrtf(__fadd_rn(tau, EPSF));
    float su = __uint_as_float(__float_as_uint(S) + 1);   // nextup(S)
    ub = __fmul_ru(su, su);                               // conservative d2+eps bound
  }

  // phase 2: rescan, ballot-compact accepted into per-warp shared buffer
  int cnt = 0;
  #pragma unroll 4
  for (int t=0; t<64; t++){
    int j = lane + 32*t;
    float4 r = __ldg(&Rb[j]);
    float dt = __fmaf_rn(q.y, r.y, __fmul_rn(q.x, r.x));
    float d  = fmaxf(__fsub_rn(__fadd_rn(q.z, r.z), __fmul_rn(2.0f, dt)), 0.0f);
    if (MASKC){
      unsigned wv = __shfl_sync(FULL, (t<32)?w0:w1, t&31);
      if (!((wv>>lane)&1u)) d = BIGF;
    }
    if (EYE){ if (j == i) d = __fadd_rn(d, BIGF); }
    bool acc;
    if (SQRT) acc = (__fadd_rn(d, EPSF) < ub);
    else      acc = (d <= tau);
    unsigned bal = __ballot_sync(FULL, acc);
    if (acc){
      int pos = cnt + __popc(bal & ((1u<<lane)-1u));
      if (pos < SCAP){
        float kd = SQRT ? sqrtf(__fadd_rn(d, EPSF)) : d;
        sbuf[pos] = ((unsigned long long)__float_as_uint(kd) << 32) | (unsigned)j;
      }
    }
    cnt += __popc(bal);
  }
  if (cnt > SCAP){
    warp_topk_ins<K,MASKC,EYE,SQRT>(Q, R, mbits, row, out);
    return;
  }
  __syncwarp();
  // phase 3: exact K-round extraction over <=SCAP unique keys
  unsigned long long mk[SCAP/32];
  #pragma unroll
  for (int u=0; u<SCAP/32; u++){
    int idx = lane + 32*u;
    mk[u] = (idx < cnt) ? sbuf[idx] : INFK;
  }
  #pragma unroll
  for (int s=0; s<K; s++){
    unsigned long long lm = mk[0]; int slot = 0;
    #pragma unroll
    for (int u=1; u<SCAP/32; u++) if (mk[u] < lm){ lm = mk[u]; slot = u; }
    unsigned long long g = lm;
    #pragma unroll
    for (int off=16; off; off>>=1){
      unsigned long long o = __shfl_xor_sync(FULL, g, off);
      g = (o < g) ? o : g;
    }
    out[s] = g;
    if (lm == g){
      #pragma unroll
      for (int u=0; u<SCAP/32; u++) if (u == slot) mk[u] = INFK;
    }
  }
}

// ---------------- dual self-KNN12: rows [0,BN) on xy1, [BN,2BN) on xy2 ----------
__global__ void k_knn12(){
  __shared__ unsigned long long sb[WPB*SCAP];
  int w = threadIdx.x >> 5;
  int row2 = blockIdx.x*WPB + w;
  if (row2 >= 2*BN) return;
  bool is1 = row2 < BN;
  int row = is1 ? row2 : row2 - BN;
  const float4* P = is1 ? g_xy1p : g_xy2p;
  int* oIdx = is1 ? g_nbA : g_nbB;
  unsigned long long out[12];
  warp_topk2<12,false,false,false>(P, P, nullptr, row, sb + w*SCAP, out);
  if ((threadIdx.x & 31) == 0){
    #pragma unroll
    for (int s=0; s<12; s++) oIdx[row*12+s] = (int)(out[s] & 0xFFFFFFFFu);
  }
}

// ---------------- knn4 candidates + feature K entries + slot order (fused) --------
__global__ void k_knn4kc(int useflow){
  __shared__ unsigned long long sb[WPB*SCAP];
  int w = threadIdx.x >> 5;
  int lane = threadIdx.x & 31;
  int row = blockIdx.x*WPB + w;
  if (row >= BN) return;
  int b = row >> 11;
  const float4* Q = useflow ? g_xy11p : g_xy1p;
  unsigned long long out[4];
  warp_topk2<4,false,false,false>(Q, g_xy2p, nullptr, row, sb + w*SCAP, out);

  // feature dots on the 4 candidates (warp-parallel, R4-validated ordering)
  const float* f1 = g_f1n + (size_t)row*C_;
  float a[16];
  #pragma unroll
  for (int t=0; t<16; t++) a[t] = f1[lane + 32*t];
  float eps = g_par[0];
  #pragma unroll
  for (int c=0; c<4; c++){
    int j = (int)(out[c] & 0xFFFFFFFFu);
    const float* f2 = g_f2n + ((size_t)(b*N_ + j))*C_;
    float s = 0.f;
    #pragma unroll
    for (int t=0; t<16; t++) s = __fadd_rn(s, __fmul_rn(a[t], __ldg(&f2[lane + 32*t])));
    #pragma unroll
    for (int off=16; off; off>>=1) s = __fadd_rn(s, __shfl_xor_sync(0xffffffffu, s, off));
    if (lane == 0){
      g_cand[row*4+c] = j;
      g_Kc[row*4+c] = expf(__fdiv_rn(-(__fsub_rn(1.0f, s)), eps));
    }
  }
  if (lane == 0){
    int k0 = ((int)(out[0]&0xFFFFFFFFu)<<2)|0, k1 = ((int)(out[1]&0xFFFFFFFFu)<<2)|1;
    int k2 = ((int)(out[2]&0xFFFFFFFFu)<<2)|2, k3 = ((int)(out[3]&0xFFFFFFFFu)<<2)|3;
    int t;
    if (k0>k1){t=k0;k0=k1;k1=t;} if (k2>k3){t=k2;k2=k3;k3=t;}
    if (k0>k2){t=k0;k0=k2;k2=t;} if (k1>k3){t=k1;k1=k3;k3=t;}
    if (k1>k2){t=k1;k1=k2;k2=t;}
    g_sord[row] = (k0&3) | ((k1&3)<<2) | ((k2&3)<<4) | ((k3&3)<<6);
  }
}

// ---------------- all 4 sinkhorn rounds in one launch; ctbuild in shared ----------
// grid (B_, 4); block 1024; dyn smem 80KB
__global__ void k_sinkhorn_all(){
  extern __shared__ char sm[];
  unsigned long long* ck = (unsigned long long*)sm;         // 16KB
  float* su  = (float*)(sm + 16384);                        // 8KB
  float* sv  = (float*)(sm + 24576);                        // 8KB
  int*   tl  = (int*)(sm + 32768);                          // 32KB
  int*   coff= (int*)(sm + 65536);                          // 8KB
  int*   ccnt= (int*)(sm + 73728);                          // 8KB
  int*   scnt= (int*)ck;                                    // overlay (build phase)
  int*   scur= scnt + N_;

  int b = blockIdx.x, r = blockIdx.y, dr0 = r + 1, tid = threadIdx.x;
  const int* cb = g_cand + b*N_*4;
  const float* Kb = g_Kc + b*N_*4;
  const int* sob = g_sord + b*N_;
  const float P = 1.0f/2048.0f;
  float pw = g_par[1];

  // --- build transpose list in shared ---
  scnt[tid] = 0; scnt[tid+1024] = 0;
  __syncthreads();
  #pragma unroll
  for (int rr=0; rr<2; rr++){
    int i = tid + rr*1024;
    #pragma unroll
    for (int c=0; c<4; c++) atomicAdd(&scnt[cb[i*4+c]], 1);
  }
  __syncthreads();
  if (tid < 32){
    int lo = tid*64, tot = 0;
    for (int t=0; t<64; t++) tot += scnt[lo+t];
    int inc = tot;
    #pragma unroll
    for (int off=1; off<32; off<<=1){
      int v = __shfl_up_sync(0xffffffffu, inc, off);
      if (tid >= off) inc += v;
    }
    int run = inc - tot;
    for (int t=0; t<64; t++){
      coff[lo+t] = run;
      ccnt[lo+t] = scnt[lo+t];
      run += scnt[lo+t];
    }
  }
  __syncthreads();
  scur[tid] = coff[tid]; scur[tid+1024] = coff[tid+1024];
  __syncthreads();
  #pragma unroll
  for (int rr=0; rr<2; rr++){
    int i = tid + rr*1024;
    #pragma unroll
    for (int c=0; c<4; c++){
      int j = cb[i*4+c];
      int pos = atomicAdd(&scur[j], 1);
      tl[pos] = (i<<2) | c;
    }
  }
  __syncthreads();
  #pragma unroll
  for (int rr=0; rr<2; rr++){
    int col = tid + rr*1024;
    int off = coff[col], cnt = ccnt[col];
    int* L = tl + off;
    for (int a2=1; a2<cnt; a2++){
      int v = L[a2]; int p = a2-1;
      while (p >= 0 && L[p] > v){ L[p+1] = L[p]; p--; }
      L[p+1] = v;
    }
  }
  __syncthreads();

  // --- sinkhorn (5 iters) ---
  sv[tid] = 1.f; sv[tid+1024] = 1.f;
  __syncthreads();
  for (int t=0; t<5; t++){
    #pragma unroll
    for (int rr=0; rr<2; rr++){
      int i = tid + rr*1024;
      int o = sob[i];
      float s = 0.f;
      #pragma unroll
      for (int p=0; p<4; p++){
        int sl = (o >> (2*p)) & 3;
        if (sl < dr0)
          s = __fmaf_rn(Kb[i*4+sl], sv[cb[i*4+sl]], s);
      }
      su[i] = powf(__fdiv_rn(P, __fadd_rn(s, EPSF)), pw);
    }
    __syncthreads();
    #pragma unroll
    for (int rr=0; rr<2; rr++){
      int j = tid + rr*1024;
      int off = coff[j], cnt = ccnt[j];
      float s = 0.f;
      for (int p=0; p<cnt; p++){
        int e = tl[off+p];
        int c = e & 3;
        if (c < dr0){
          int i = e >> 2;
          s = __fmaf_rn(Kb[i*4+c], su[i], s);
        }
      }
      sv[j] = powf(__fdiv_rn(P, __fadd_rn(s, EPSF)), pw);
    }
    __syncthreads();
  }

  // --- mutual-best recon ---
  ck[tid] = 0xFFFFFFFFull; ck[tid+1024] = 0xFFFFFFFFull;
  __syncthreads();
  #pragma unroll
  for (int rr=0; rr<2; rr++){
    int i = tid + rr*1024;
    float ui = su[i];
    for (int c=0; c<dr0; c++){
      int j = cb[i*4+c];
      float tv = __fmul_rn(__fmul_rn(ui, Kb[i*4+c]), sv[j]);
      unsigned long long key = ((unsigned long long)__float_as_uint(tv) << 32)
                             | (unsigned)(~(unsigned)i);
      atomicMax(&ck[j], key);
    }
  }
  __syncthreads();
  #pragma unroll
  for (int rr=0; rr<2; rr++){
    int i = tid + rr*1024;
    float ui = su[i];
    unsigned long long k0 = 0ull, k1 = 0ull;
    for (int c=0; c<dr0; c++){
      int j = cb[i*4+c];
      float tv = __fmul_rn(__fmul_rn(ui, Kb[i*4+c]), sv[j]);
      unsigned long long key = ((unsigned long long)__float_as_uint(tv) << 32)
                             | (unsigned)(~(unsigned)j);
      if (key > k0){ k1 = k0; k0 = key; }
      else if (key > k1){ k1 = key; }
    }
    float rv0 = __uint_as_float((unsigned)(k0 >> 32));
    float rv1 = __uint_as_float((unsigned)(k1 >> 32));
    int bj = (int)(~(unsigned)k0);
    int bi = (int)(~(unsigned)ck[bj]);
    bool ok = rv0 > __fmul_rn(1.2f, rv1);
    g_idx0R[r*BN + b*N_ + i] = (bi == i && ok) ? bj : -1;
  }
}

// ---------------- merge (+optional knn recon) + similarity verify + bitpack --------
template<int SIMK, int MODE>
__global__ void k_simmerge(const float* __restrict__ xy1, const float* __restrict__ xy2,
                           int r){
  int row = blockIdx.x*blockDim.x + threadIdx.x;
  int b = row / N_, i = row - b*N_;
  int m;
  if (MODE == 0) m = g_idx0R[r*BN + row];
  else if (MODE == 1){ int p = g_idx1[row]; m = (p == 0) ? g_idx0R[r*BN + row] : (p - 1); }
  else {
    float d0 = g_rowD[row*2], d1 = g_rowD[row*2+1];
    int bj = g_rowIdx[row*2];
    bool ok = __fmul_rn(d0, 1.2f) < d1;
    bool mut = (g_colArg[b*N_ + bj] == i);
    m = (ok && mut) ? bj : -1;
  }

  int outv = -1;
  if (m >= 0){
    const float* X1 = xy1 + (size_t)b*N_*2;
    const float* X2 = xy2 + (size_t)b*N_*2;
    float pix = X1[i*2], piy = X1[i*2+1];
    float pjx = X2[m*2], pjy = X2[m*2+1];
    float o1x[SIMK], o1y[SIMK], o2x[SIMK], o2y[SIMK];
    #pragma unroll
    for (int k=0; k<SIMK; k++){
      int a = g_nbA[row*12 + 1 + k];
      o1x[k] = __fsub_rn(X1[a*2],   pix);
      o1y[k] = __fsub_rn(X1[a*2+1], piy);
      int c = g_nbB[(b*N_+m)*12 + 1 + k];
      o2x[k] = __fsub_rn(X2[c*2],   pjx);
      o2y[k] = __fsub_rn(X2[c*2+1], pjy);
    }
    float colmin[SIMK];
    #pragma unroll
    for (int l=0; l<SIMK; l++) colmin[l] = 3.4e38f;
    float sum1 = 0.f;
    #pragma unroll
    for (int k=0; k<SIMK; k++){
      float rmn = 3.4e38f;
      #pragma unroll
      for (int l=0; l<SIMK; l++){
        float dx = __fsub_rn(o1x[k], o2x[l]);
        float dy = __fsub_rn(o1y[k], o2y[l]);
        float d = sqrtf(__fadd_rn(__fmaf_rn(dy, dy, __fmul_rn(dx, dx)), EPSF));
        rmn = fminf(rmn, d);
        colmin[l] = fminf(colmin[l], d);
      }
      sum1 = __fadd_rn(sum1, rmn);
    }
    float sum2 = 0.f;
    #pragma unroll
    for (int l=0; l<SIMK; l++) sum2 = __fadd_rn(sum2, colmin[l]);
    float Kf = (float)SIMK;
    float cham = __fmul_rn(0.5f, __fadd_rn(__fdiv_rn(sum1, Kf), __fdiv_rn(sum2, Kf)));
    if (cham <= 2.0f) outv = m;
  }
  g_idxA[row] = outv;
  int mm = (outv >= 0);
  g_maskA[row] = mm;
  int j = (outv >= 0) ? outv : 0;
  float mf = (float)mm;
  g_flow[row*2]   = __fmul_rn(__fsub_rn(xy2[(b*N_+j)*2],   xy1[row*2]),   mf);
  g_flow[row*2+1] = __fmul_rn(__fsub_rn(xy2[(b*N_+j)*2+1], xy1[row*2+1]), mf);
  unsigned bal = __ballot_sync(0xffffffffu, mm);
  if ((threadIdx.x & 31) == 0) g_bitsA[row >> 5] = bal;
}

// ---------------- masked topk(8)+eye + outlier rejection ----------
__global__ void k_outlier(){
  __shared__ unsigned long long sb[WPB*SCAP];
  int w = threadIdx.x >> 5;
  int row = blockIdx.x*WPB + w;
  if (row >= BN) return;
  unsigned long long out[8];
  warp_topk2<8,true,true,false>(g_xy1p, g_xy1p, g_bitsA, row, sb + w*SCAP, out);
  if ((threadIdx.x & 31) == 0){
    int b = row / N_;
    float fx = g_flow[row*2], fy = g_flow[row*2+1];
    float sx = 0.f, sy = 0.f, cnt = 0.f;
    #pragma unroll
    for (int s=0; s<8; s++){
      float d = __uint_as_float((unsigned)(out[s] >> 32));
      float vf = (d < 5e8f) ? 1.0f : 0.0f;
      int j = (d < 5e8f) ? (int)(out[s] & 0xFFFFFFFFu) : 0;
      sx = __fmaf_rn(g_flow[(b*N_+j)*2],   vf, sx);
      sy = __fmaf_rn(g_flow[(b*N_+j)*2+1], vf, sy);
      cnt = __fadd_rn(cnt, vf);
    }
    float dv = fmaxf(cnt, 1.0f);
    float mx = __fdiv_rn(sx, dv), my = __fdiv_rn(sy, dv);
    float ddx = __fsub_rn(fx, mx), ddy = __fsub_rn(fy, my);
    float dev = sqrtf(__fadd_rn(__fmaf_rn(ddy, ddy, __fmul_rn(ddx, ddx)), EPSF));
    int mi = g_maskA[row];
    bool keep = mi && ((cnt > 0.0f) ? (dev <= 2.0f) : true);
    g_idx1[row] = keep ? (g_idxA[row] + 1) : 0;
  }
}

__global__ void k_dedup(){
  __shared__ int cnt[N_+1];
  int b = blockIdx.x, tid = threadIdx.x;
  for (int s = tid; s < N_+1; s += 1024) cnt[s] = 0;
  __syncthreads();
  int v0 = g_idx1[b*N_ + tid], v1 = g_idx1[b*N_ + tid + 1024];
  atomicAdd(&cnt[v0], 1); atomicAdd(&cnt[v1], 1);
  __syncthreads();
  if (cnt[v0] > 1) g_idx1[b*N_ + tid] = 0;
  if (cnt[v1] > 1) g_idx1[b*N_ + tid + 1024] = 0;
}

__global__ void k_finish(const float* __restrict__ xy1, const float* __restrict__ xy2,
                         float* __restrict__ outp, int withmask){
  int row = blockIdx.x*blockDim.x + threadIdx.x;
  int b = row / N_;
  int v = g_idx1[row];
  int mm = (v != 0);
  int j = (v - 1) * mm;
  float mf = (float)mm;
  float fx = __fmul_rn(__fsub_rn(xy2[(b*N_+j)*2],   xy1[row*2]),   mf);
  float fy = __fmul_rn(__fsub_rn(xy2[(b*N_+j)*2+1], xy1[row*2+1]), mf);
  g_flow[row*2] = fx; g_flow[row*2+1] = fy;
  g_mask[row] = mm;
  if (outp){
    outp[row*2] = fx; outp[row*2+1] = fy;
    if (withmask) outp[2*BN + row] = mf;
  }
  unsigned bal = __ballot_sync(0xffffffffu, mm);
  if ((threadIdx.x & 31) == 0) g_bitsM[row >> 5] = bal;
}

// ---------------- masked topk(4) + IDW interp + xy11 prep (fused) ----------
__global__ void k_griddata(){
  __shared__ unsigned long long sb[WPB*SCAP];
  int w = threadIdx.x >> 5;
  int row = blockIdx.x*WPB + w;
  if (row >= BN) return;
  unsigned long long out[4];
  warp_topk2<4,true,false,false>(g_xy1p, g_xy1p, g_bitsM, row, sb + w*SCAP, out);
  if ((threadIdx.x & 31) == 0){
    int b = row / N_;
    float ws = 0.f, sx = 0.f, sy = 0.f;
    #pragma unroll
    for (int s=0; s<4; s++){
      float d = __uint_as_float((unsigned)(out[s] >> 32));
      float vf = (d < 5e8f) ? 1.0f : 0.0f;
      int j = (d < 5e8f) ? (int)(out[s] & 0xFFFFFFFFu) : 0;
      float wt = __fdiv_rn(vf, __fadd_rn(d, 1e-6f));
      sx = __fmaf_rn(wt, g_flow[(b*N_+j)*2],   sx);
      sy = __fmaf_rn(wt, g_flow[(b*N_+j)*2+1], sy);
      ws = __fadd_rn(ws, wt);
    }
    float ix = __fdiv_rn(sx, __fadd_rn(ws, EPSF));
    float iy = __fdiv_rn(sy, __fadd_rn(ws, EPSF));
    int m = g_mask[row];
    float gx = m ? g_flow[row*2]   : ix;
    float gy = m ? g_flow[row*2+1] : iy;
    // fused xy11 prep: x' = x + flow_gri (same formula as reference xy11)
    float4 p = g_xy1p[row];
    float nx = __fadd_rn(p.x, gx);
    float ny = __fadd_rn(p.y, gy);
    g_xy11p[row] = make_float4(nx, ny, __fmaf_rn(ny, ny, __fmul_rn(nx, nx)), 0.f);
  }
}

// ---------------- dual knn_match scans: row top-2 and col top-1 (D space) ----------
__global__ void k_knn21(){
  __shared__ unsigned long long sb[WPB*SCAP];
  int w = threadIdx.x >> 5;
  int row2 = blockIdx.x*WPB + w;
  if (row2 >= 2*BN) return;
  bool first = row2 < BN;
  int row = first ? row2 : row2 - BN;
  const float4* Q = first ? g_xy11p : g_xy2p;
  const float4* R = first ? g_xy2p  : g_xy11p;
  unsigned long long out[2];
  warp_topk2<2,false,false,true>(Q, R, nullptr, row, sb + w*SCAP, out);
  if ((threadIdx.x & 31) == 0){
    if (first){
      g_rowIdx[row*2]   = (int)(out[0] & 0xFFFFFFFFu);
      g_rowIdx[row*2+1] = (int)(out[1] & 0xFFFFFFFFu);
      g_rowD[row*2]   = __uint_as_float((unsigned)(out[0] >> 32));
      g_rowD[row*2+1] = __uint_as_float((unsigned)(out[1] >> 32));
    } else {
      g_colArg[row] = (int)(out[0] & 0xFFFFFFFFu);
    }
  }
}

// ---------------- host orchestration ----------------
extern "C" void kernel_launch(void* const* d_in, const int* in_sizes, int n_in,
                              void* d_out, int out_size){
  const float* xy1 = (const float*)d_in[0];
  const float* xy2 = (const float*)d_in[1];
  const float* f1  = (const float*)d_in[2];
  const float* f2  = (const float*)d_in[3];
  const float* gam = (const float*)d_in[4];
  const float* eps = (const float*)d_in[5];
  float* outp = (float*)d_out;
  int withmask = (out_size >= BN*3) ? 1 : 0;

  static bool attr_done = false;
  if (!attr_done){
    cudaFuncSetAttribute(k_sinkhorn_all, cudaFuncAttributeMaxDynamicSharedMemorySize, 81920);
    attr_done = true;
  }

  const int WB = WPB*32;            // 256 threads
  const int GW = BN/WPB;            // 512 blocks (BN rows)
  const int GW2 = 2*BN/WPB;         // 1024 blocks (2BN rows)
  const int TB = 256, GT = BN/TB;

  k_init<<<(2*BN*32)/256, 256>>>(f1, f2, gam, eps);
  k_prep2<<<(2*BN)/256, 256>>>(xy1, xy2);
  k_knn12<<<GW2, WB>>>();

  // ---- two sinkhorn matching passes ----
  for (int pass = 0; pass < 2; pass++){
    k_knn4kc<<<GW, WB>>>(pass);
    k_sinkhorn_all<<<dim3(B_,4), 1024, 81920>>>();
    for (int r = 0; r < 4; r++){
      if (r == 0) k_simmerge<8,0><<<GT, TB>>>(xy1, xy2, r);
      else        k_simmerge<8,1><<<GT, TB>>>(xy1, xy2, r);
      k_outlier<<<GW, WB>>>();
      if (r > 0) k_dedup<<<2, 1024>>>();
    }
    k_finish<<<GT, TB>>>(xy1, xy2, nullptr, 0);
    k_griddata<<<GW, WB>>>();
  }

  // ---- two KNN matching passes ----
  for (int pass = 0; pass < 2; pass++){
    int final = (pass == 1);
    k_knn21<<<GW2, WB>>>();
    k_simmerge<11,2><<<GT, TB>>>(xy1, xy2, 0);
    k_outlier<<<GW, WB>>>();
    k_finish<<<GT, TB>>>(xy1, xy2, final ? outp : nullptr, withmask);
    if (!final) k_griddata<<<GW, WB>>>();
  }
}

// round 10
// speedup vs baseline: 3.0972x; 1.0817x over previous
#include <cuda_runtime.h>
#include <stdint.h>
#include <math.h>

#define N_   2048
#define B_   2
#define C_   512
#define BN   (B_*N_)
#define EPSF 1e-8f
#define BIGF 1e9f
#define WPB  8          // warps per scan block

// ---------------- device scratch ----------------
__device__ float  g_f1n[BN*C_], g_f2n[BN*C_];
__device__ float4 g_xy1p[BN], g_xy2p[BN], g_xy11p[BN];   // (x, y, rb, 0)
__device__ int    g_nbA[BN*12], g_nbB[BN*12];
__device__ int    g_nn1i[BN*32];
__device__ float  g_nn1d[BN*32];
__device__ int    g_cand[BN*4];
__device__ float  g_Kc[BN*4];
__device__ int    g_sord[BN];
__device__ int    g_idx0R[4*BN];
__device__ int    g_idxA[BN], g_maskA[BN], g_idx1[BN], g_mask[BN];
__device__ unsigned g_bitsA[B_*(N_/32)], g_bitsM[B_*(N_/32)];
__device__ int    g_cnt[64];
__device__ float  g_flow[BN*2];
__device__ float  g_rowD[BN*2];
__device__ int    g_rowIdx[BN*2];
__device__ int    g_colArg[BN];
__device__ float  g_par[2];   // [0]=eps, [1]=power

// ---------------- init: params + counters + feature norms + normalize ----------------
__global__ void k_init(const float* __restrict__ f1, const float* __restrict__ f2,
                       const float* __restrict__ gam, const float* __restrict__ eps){
  int gt = blockIdx.x*blockDim.x + threadIdx.x;
  int gw = gt >> 5;
  int lane = threadIdx.x & 31;
  if (gt < 64) g_cnt[gt] = 0;
  if (gt == 64){
    float e = __fadd_rn(expf(eps[0]), 0.03f);
    float g = expf(gam[0]);
    g_par[0] = e;
    g_par[1] = __fdiv_rn(g, __fadd_rn(g, e));
  }
  if (gw >= 2*BN) return;
  bool is1 = gw < BN;
  int row = is1 ? gw : gw - BN;
  const float* f = (is1 ? f1 : f2) + (size_t)row*C_;
  float*       o = (is1 ? g_f1n : g_f2n) + (size_t)row*C_;
  float v[16];
  float s = 0.f;
  #pragma unroll
  for (int t=0; t<16; t++){ v[t] = f[lane + 32*t]; s = __fmaf_rn(v[t], v[t], s); }
  #pragma unroll
  for (int off=16; off; off>>=1) s = __fadd_rn(s, __shfl_xor_sync(0xffffffffu, s, off));
  float n = __fadd_rn(sqrtf(s), EPSF);
  #pragma unroll
  for (int t=0; t<16; t++) o[lane + 32*t] = __fdiv_rn(v[t], n);
}

__global__ void k_prep2(const float* __restrict__ xy1, const float* __restrict__ xy2){
  int p = blockIdx.x*blockDim.x + threadIdx.x;
  if (p >= 2*BN) return;
  bool is1 = p < BN;
  int row = is1 ? p : p - BN;
  const float* xy = is1 ? xy1 : xy2;
  float x = xy[row*2], y = xy[row*2+1];
  float4 v = make_float4(x, y, __fmaf_rn(y, y, __fmul_rn(x, x)), 0.f);
  if (is1) g_xy1p[row] = v; else g_xy2p[row] = v;
}

// ---------------- fallback: insertion-sort warp top-K (rare; bit-identical) --------
template<int K, bool MASKC, bool EYE, bool SQRT>
__device__ __noinline__ void warp_topk_ins(
    const float4* __restrict__ Q, const float4* __restrict__ R,
    const unsigned* __restrict__ mbits, int row, unsigned long long (&out)[K])
{
  const unsigned FULL = 0xffffffffu;
  int lane = threadIdx.x & 31;
  int b = row >> 11, i = row & (N_-1);
  float4 q = __ldg(&Q[row]);
  const float4* Rb = R + (size_t)b*N_;
  unsigned w0 = FULL, w1 = FULL;
  if (MASKC){
    const unsigned* mb = mbits + b*(N_/32);
    w0 = __ldg(&mb[lane]); w1 = __ldg(&mb[32+lane]);
  }
  unsigned long long best[K];
  #pragma unroll
  for (int s=0; s<K; s++) best[s] = 0x7F800000FFFFFFFFull;
  float dlast = __uint_as_float(0x7F800000u);
  float U     = __uint_as_float(0x7FC00000u);

  for (int t=0; t<64; t++){
    int j = lane + 32*t;
    float4 r = __ldg(&Rb[j]);
    float dt = __fmaf_rn(q.y, r.y, __fmul_rn(q.x, r.x));
    float d  = fmaxf(__fsub_rn(__fadd_rn(q.z, r.z), __fmul_rn(2.0f, dt)), 0.0f);
    if (MASKC){
      unsigned wv = __shfl_sync(FULL, (t<32)?w0:w1, t&31);
      if (!((wv>>lane)&1u)) d = BIGF;
    }
    if (EYE){ if (j == i) d = __fadd_rn(d, BIGF); }
    bool try_ins;
    if (SQRT){
      float d2pe = __fadd_rn(d, EPSF);
      try_ins = !(d2pe > U);
      if (try_ins) d = sqrtf(d2pe);
    } else try_ins = (d <= dlast);
    if (try_ins){
      unsigned long long key = ((unsigned long long)__float_as_uint(d) << 32) | (unsigned)j;
      if (key < best[K-1]){
        best[K-1] = key;
        #pragma unroll
        for (int s=K-1; s>0; s--){
          if (best[s] < best[s-1]){
            unsigned long long tmp = best[s-1]; best[s-1] = best[s]; best[s] = tmp;
          } else break;
        }
        unsigned hb = (unsigned)(best[K-1] >> 32);
        if (SQRT){
          float up = __uint_as_float(hb + 1);
          U = __fmul_ru(up, up);
        } else dlast = __uint_as_float(hb);
      }
    }
  }
  #pragma unroll
  for (int s=0; s<K; s++){
    unsigned long long c = best[0];
    unsigned long long m = c;
    #pragma unroll
    for (int off=16; off; off>>=1){
      unsigned long long o = __shfl_xor_sync(FULL, m, off);
      m = (o < m) ? o : m;
    }
    if (c == m){
      #pragma unroll
      for (int u=0; u<K-1; u++) best[u] = best[u+1];
      best[K-1] = 0x7F800000FFFFFFFFull;
    }
    out[s] = m;
  }
}

// ---------------- two-phase divergence-free exact warp top-K ----------------
template<int K, int CAP, bool MASKC, bool EYE, bool SQRT>
__device__ __forceinline__ void warp_topk2(
    const float4* __restrict__ Q, const float4* __restrict__ R,
    const unsigned* __restrict__ mbits, int row,
    unsigned long long* __restrict__ sbuf, unsigned long long (&out)[K])
{
  const unsigned FULL = 0xffffffffu;
  const unsigned long long INFK = 0x7F800000FFFFFFFFull;
  int lane = threadIdx.x & 31;
  int b = row >> 11, i = row & (N_-1);
  float4 q = __ldg(&Q[row]);
  const float4* Rb = R + (size_t)b*N_;
  unsigned w0 = FULL, w1 = FULL;
  if (MASKC){
    const unsigned* mb = mbits + b*(N_/32);
    w0 = __ldg(&mb[lane]); w1 = __ldg(&mb[32+lane]);
  }

  // phase 1: per-lane min of modified d2 (branchless)
  float mn = __uint_as_float(0x7F800000u);
  #pragma unroll 4
  for (int t=0; t<64; t++){
    int j = lane + 32*t;
    float4 r = __ldg(&Rb[j]);
    float dt = __fmaf_rn(q.y, r.y, __fmul_rn(q.x, r.x));
    float d  = fmaxf(__fsub_rn(__fadd_rn(q.z, r.z), __fmul_rn(2.0f, dt)), 0.0f);
    if (MASKC){
      unsigned wv = __shfl_sync(FULL, (t<32)?w0:w1, t&31);
      if (!((wv>>lane)&1u)) d = BIGF;
    }
    if (EYE){ if (j == i) d = __fadd_rn(d, BIGF); }
    mn = fminf(mn, d);
  }
  // tau = K-th smallest of the 32 lane minima
  float v = mn, tau = 0.f;
  #pragma unroll
  for (int s=0; s<K; s++){
    float g = v;
    #pragma unroll
    for (int off=16; off; off>>=1) g = fminf(g, __shfl_xor_sync(FULL, g, off));
    tau = g;
    unsigned hit = __ballot_sync(FULL, v == g);
    if (lane == (__ffs(hit)-1)) v = __uint_as_float(0x7F800000u);
  }
  float ub = 0.f;
  if (SQRT){
    float S  = sqrtf(__fadd_rn(tau, EPSF));
    float su = __uint_as_float(__float_as_uint(S) + 1);
    ub = __fmul_ru(su, su);
  }

  // phase 2: rescan, ballot-compact accepted into shared buffer
  int cnt = 0;
  #pragma unroll 4
  for (int t=0; t<64; t++){
    int j = lane + 32*t;
    float4 r = __ldg(&Rb[j]);
    float dt = __fmaf_rn(q.y, r.y, __fmul_rn(q.x, r.x));
    float d  = fmaxf(__fsub_rn(__fadd_rn(q.z, r.z), __fmul_rn(2.0f, dt)), 0.0f);
    if (MASKC){
      unsigned wv = __shfl_sync(FULL, (t<32)?w0:w1, t&31);
      if (!((wv>>lane)&1u)) d = BIGF;
    }
    if (EYE){ if (j == i) d = __fadd_rn(d, BIGF); }
    bool acc;
    if (SQRT) acc = (__fadd_rn(d, EPSF) < ub);
    else      acc = (d <= tau);
    unsigned bal = __ballot_sync(FULL, acc);
    if (acc){
      int pos = cnt + __popc(bal & ((1u<<lane)-1u));
      if (pos < CAP){
        float kd = SQRT ? sqrtf(__fadd_rn(d, EPSF)) : d;
        sbuf[pos] = ((unsigned long long)__float_as_uint(kd) << 32) | (unsigned)j;
      }
    }
    cnt += __popc(bal);
  }
  if (cnt > CAP){
    warp_topk_ins<K,MASKC,EYE,SQRT>(Q, R, mbits, row, out);
    return;
  }
  __syncwarp();
  // phase 3: exact K-round extraction over <=CAP unique keys
  unsigned long long mk[CAP/32];
  #pragma unroll
  for (int u=0; u<CAP/32; u++){
    int idx = lane + 32*u;
    mk[u] = (idx < cnt) ? sbuf[idx] : INFK;
  }
  #pragma unroll
  for (int s=0; s<K; s++){
    unsigned long long lm = mk[0]; int slot = 0;
    #pragma unroll
    for (int u=1; u<CAP/32; u++) if (mk[u] < lm){ lm = mk[u]; slot = u; }
    unsigned long long g = lm;
    #pragma unroll
    for (int off=16; off; off>>=1){
      unsigned long long o = __shfl_xor_sync(FULL, g, off);
      g = (o < g) ? o : g;
    }
    out[s] = g;
    if (lm == g){
      #pragma unroll
      for (int u=0; u<CAP/32; u++) if (u == slot) mk[u] = INFK;
    }
  }
}

// ---------------- precompute: top-32 self list on xy1 (+nbA), top-12 on xy2 --------
__global__ void k_knnpre(){
  __shared__ unsigned long long sb[WPB*256];
  int w = threadIdx.x >> 5;
  int row2 = blockIdx.x*WPB + w;
  if (row2 >= 2*BN) return;
  if (row2 < BN){
    int row = row2;
    unsigned long long out[32];
    warp_topk2<32,256,false,false,false>(g_xy1p, g_xy1p, nullptr, row, sb + w*256, out);
    if ((threadIdx.x & 31) == 0){
      #pragma unroll
      for (int s=0; s<32; s++){
        int jj = (int)(out[s] & 0xFFFFFFFFu);
        g_nn1i[row*32+s] = jj;
        g_nn1d[row*32+s] = __uint_as_float((unsigned)(out[s] >> 32));
        if (s < 12) g_nbA[row*12+s] = jj;
      }
    }
  } else {
    int row = row2 - BN;
    unsigned long long out[12];
    warp_topk2<12,128,false,false,false>(g_xy2p, g_xy2p, nullptr, row, sb + w*256, out);
    if ((threadIdx.x & 31) == 0){
      #pragma unroll
      for (int s=0; s<12; s++) g_nbB[row*12+s] = (int)(out[s] & 0xFFFFFFFFu);
    }
  }
}

// ---------------- knn4 candidates + feature K entries + slot order (fused) --------
__global__ void k_knn4kc(int useflow){
  __shared__ unsigned long long sb[WPB*128];
  int w = threadIdx.x >> 5;
  int lane = threadIdx.x & 31;
  int row = blockIdx.x*WPB + w;
  if (row >= BN) return;
  int b = row >> 11;
  const float4* Q = useflow ? g_xy11p : g_xy1p;
  unsigned long long out[4];
  warp_topk2<4,128,false,false,false>(Q, g_xy2p, nullptr, row, sb + w*128, out);

  const float* f1 = g_f1n + (size_t)row*C_;
  float a[16];
  #pragma unroll
  for (int t=0; t<16; t++) a[t] = f1[lane + 32*t];
  float eps = g_par[0];
  #pragma unroll
  for (int c=0; c<4; c++){
    int j = (int)(out[c] & 0xFFFFFFFFu);
    const float* f2 = g_f2n + ((size_t)(b*N_ + j))*C_;
    float s = 0.f;
    #pragma unroll
    for (int t=0; t<16; t++) s = __fadd_rn(s, __fmul_rn(a[t], __ldg(&f2[lane + 32*t])));
    #pragma unroll
    for (int off=16; off; off>>=1) s = __fadd_rn(s, __shfl_xor_sync(0xffffffffu, s, off));
    if (lane == 0){
      g_cand[row*4+c] = j;
      g_Kc[row*4+c] = expf(__fdiv_rn(-(__fsub_rn(1.0f, s)), eps));
    }
  }
  if (lane == 0){
    int k0 = ((int)(out[0]&0xFFFFFFFFu)<<2)|0, k1 = ((int)(out[1]&0xFFFFFFFFu)<<2)|1;
    int k2 = ((int)(out[2]&0xFFFFFFFFu)<<2)|2, k3 = ((int)(out[3]&0xFFFFFFFFu)<<2)|3;
    int t;
    if (k0>k1){t=k0;k0=k1;k1=t;} if (k2>k3){t=k2;k2=k3;k3=t;}
    if (k0>k2){t=k0;k0=k2;k2=t;} if (k1>k3){t=k1;k1=k3;k3=t;}
    if (k1>k2){t=k1;k1=k2;k2=t;}
    g_sord[row] = (k0&3) | ((k1&3)<<2) | ((k2&3)<<4) | ((k3&3)<<6);
  }
}

// ---------------- all 4 sinkhorn rounds in one launch ----------
__global__ void k_sinkhorn_all(){
  extern __shared__ char sm[];
  unsigned long long* ck = (unsigned long long*)sm;         // 16KB
  float* su  = (float*)(sm + 16384);
  float* sv  = (float*)(sm + 24576);
  int*   tl  = (int*)(sm + 32768);
  int*   coff= (int*)(sm + 65536);
  int*   ccnt= (int*)(sm + 73728);
  int*   scnt= (int*)ck;
  int*   scur= scnt + N_;

  int b = blockIdx.x, r = blockIdx.y, dr0 = r + 1, tid = threadIdx.x;
  const int* cb = g_cand + b*N_*4;
  const float* Kb = g_Kc + b*N_*4;
  const int* sob = g_sord + b*N_;
  const float P = 1.0f/2048.0f;
  float pw = g_par[1];

  scnt[tid] = 0; scnt[tid+1024] = 0;
  __syncthreads();
  #pragma unroll
  for (int rr=0; rr<2; rr++){
    int i = tid + rr*1024;
    #pragma unroll
    for (int c=0; c<4; c++) atomicAdd(&scnt[cb[i*4+c]], 1);
  }
  __syncthreads();
  if (tid < 32){
    int lo = tid*64, tot = 0;
    for (int t=0; t<64; t++) tot += scnt[lo+t];
    int inc = tot;
    #pragma unroll
    for (int off=1; off<32; off<<=1){
      int v = __shfl_up_sync(0xffffffffu, inc, off);
      if (tid >= off) inc += v;
    }
    int run = inc - tot;
    for (int t=0; t<64; t++){
      coff[lo+t] = run;
      ccnt[lo+t] = scnt[lo+t];
      run += scnt[lo+t];
    }
  }
  __syncthreads();
  scur[tid] = coff[tid]; scur[tid+1024] = coff[tid+1024];
  __syncthreads();
  #pragma unroll
  for (int rr=0; rr<2; rr++){
    int i = tid + rr*1024;
    #pragma unroll
    for (int c=0; c<4; c++){
      int j = cb[i*4+c];
      int pos = atomicAdd(&scur[j], 1);
      tl[pos] = (i<<2) | c;
    }
  }
  __syncthreads();
  #pragma unroll
  for (int rr=0; rr<2; rr++){
    int col = tid + rr*1024;
    int off = coff[col], cnt = ccnt[col];
    int* L = tl + off;
    for (int a2=1; a2<cnt; a2++){
      int v = L[a2]; int p = a2-1;
      while (p >= 0 && L[p] > v){ L[p+1] = L[p]; p--; }
      L[p+1] = v;
    }
  }
  __syncthreads();

  sv[tid] = 1.f; sv[tid+1024] = 1.f;
  __syncthreads();
  for (int t=0; t<5; t++){
    #pragma unroll
    for (int rr=0; rr<2; rr++){
      int i = tid + rr*1024;
      int o = sob[i];
      float s = 0.f;
      #pragma unroll
      for (int p=0; p<4; p++){
        int sl = (o >> (2*p)) & 3;
        if (sl < dr0)
          s = __fmaf_rn(Kb[i*4+sl], sv[cb[i*4+sl]], s);
      }
      su[i] = powf(__fdiv_rn(P, __fadd_rn(s, EPSF)), pw);
    }
    __syncthreads();
    #pragma unroll
    for (int rr=0; rr<2; rr++){
      int j = tid + rr*1024;
      int off = coff[j], cnt = ccnt[j];
      float s = 0.f;
      for (int p=0; p<cnt; p++){
        int e = tl[off+p];
        int c = e & 3;
        if (c < dr0){
          int i = e >> 2;
          s = __fmaf_rn(Kb[i*4+c], su[i], s);
        }
      }
      sv[j] = powf(__fdiv_rn(P, __fadd_rn(s, EPSF)), pw);
    }
    __syncthreads();
  }

  ck[tid] = 0xFFFFFFFFull; ck[tid+1024] = 0xFFFFFFFFull;
  __syncthreads();
  #pragma unroll
  for (int rr=0; rr<2; rr++){
    int i = tid + rr*1024;
    float ui = su[i];
    for (int c=0; c<dr0; c++){
      int j = cb[i*4+c];
      float tv = __fmul_rn(__fmul_rn(ui, Kb[i*4+c]), sv[j]);
      unsigned long long key = ((unsigned long long)__float_as_uint(tv) << 32)
                             | (unsigned)(~(unsigned)i);
      atomicMax(&ck[j], key);
    }
  }
  __syncthreads();
  #pragma unroll
  for (int rr=0; rr<2; rr++){
    int i = tid + rr*1024;
    float ui = su[i];
    unsigned long long k0 = 0ull, k1 = 0ull;
    for (int c=0; c<dr0; c++){
      int j = cb[i*4+c];
      float tv = __fmul_rn(__fmul_rn(ui, Kb[i*4+c]), sv[j]);
      unsigned long long key = ((unsigned long long)__float_as_uint(tv) << 32)
                             | (unsigned)(~(unsigned)j);
      if (key > k0){ k1 = k0; k0 = key; }
      else if (key > k1){ k1 = key; }
    }
    float rv0 = __uint_as_float((unsigned)(k0 >> 32));
    float rv1 = __uint_as_float((unsigned)(k1 >> 32));
    int bj = (int)(~(unsigned)k0);
    int bi = (int)(~(unsigned)ck[bj]);
    bool ok = rv0 > __fmul_rn(1.2f, rv1);
    g_idx0R[r*BN + b*N_ + i] = (bi == i && ok) ? bj : -1;
  }
}

// ---------------- merge (+optional knn recon) + similarity verify + bitpack+count ---
template<int SIMK, int MODE>
__global__ void k_simmerge(const float* __restrict__ xy1, const float* __restrict__ xy2,
                           int r, int slot){
  int row = blockIdx.x*blockDim.x + threadIdx.x;
  int b = row / N_, i = row - b*N_;
  int m;
  if (MODE == 0) m = g_idx0R[r*BN + row];
  else if (MODE == 1){ int p = g_idx1[row]; m = (p == 0) ? g_idx0R[r*BN + row] : (p - 1); }
  else {
    float d0 = g_rowD[row*2], d1 = g_rowD[row*2+1];
    int bj = g_rowIdx[row*2];
    bool ok = __fmul_rn(d0, 1.2f) < d1;
    bool mut = (g_colArg[b*N_ + bj] == i);
    m = (ok && mut) ? bj : -1;
  }

  int outv = -1;
  if (m >= 0){
    const float* X1 = xy1 + (size_t)b*N_*2;
    const float* X2 = xy2 + (size_t)b*N_*2;
    float pix = X1[i*2], piy = X1[i*2+1];
    float pjx = X2[m*2], pjy = X2[m*2+1];
    float o1x[SIMK], o1y[SIMK], o2x[SIMK], o2y[SIMK];
    #pragma unroll
    for (int k=0; k<SIMK; k++){
      int a = g_nbA[row*12 + 1 + k];
      o1x[k] = __fsub_rn(X1[a*2],   pix);
      o1y[k] = __fsub_rn(X1[a*2+1], piy);
      int c = g_nbB[(b*N_+m)*12 + 1 + k];
      o2x[k] = __fsub_rn(X2[c*2],   pjx);
      o2y[k] = __fsub_rn(X2[c*2+1], pjy);
    }
    float colmin[SIMK];
    #pragma unroll
    for (int l=0; l<SIMK; l++) colmin[l] = 3.4e38f;
    float sum1 = 0.f;
    #pragma unroll
    for (int k=0; k<SIMK; k++){
      float rmn = 3.4e38f;
      #pragma unroll
      for (int l=0; l<SIMK; l++){
        float dx = __fsub_rn(o1x[k], o2x[l]);
        float dy = __fsub_rn(o1y[k], o2y[l]);
        float d = sqrtf(__fadd_rn(__fmaf_rn(dy, dy, __fmul_rn(dx, dx)), EPSF));
        rmn = fminf(rmn, d);
        colmin[l] = fminf(colmin[l], d);
      }
      sum1 = __fadd_rn(sum1, rmn);
    }
    float sum2 = 0.f;
    #pragma unroll
    for (int l=0; l<SIMK; l++) sum2 = __fadd_rn(sum2, colmin[l]);
    float Kf = (float)SIMK;
    float cham = __fmul_rn(0.5f, __fadd_rn(__fdiv_rn(sum1, Kf), __fdiv_rn(sum2, Kf)));
    if (cham <= 2.0f) outv = m;
  }
  g_idxA[row] = outv;
  int mm = (outv >= 0);
  g_maskA[row] = mm;
  int j = (outv >= 0) ? outv : 0;
  float mf = (float)mm;
  g_flow[row*2]   = __fmul_rn(__fsub_rn(xy2[(b*N_+j)*2],   xy1[row*2]),   mf);
  g_flow[row*2+1] = __fmul_rn(__fsub_rn(xy2[(b*N_+j)*2+1], xy1[row*2+1]), mf);
  unsigned bal = __ballot_sync(0xffffffffu, mm);
  if ((threadIdx.x & 31) == 0){
    g_bitsA[row >> 5] = bal;
    atomicAdd(&g_cnt[slot*B_ + b], __popc(bal));
  }
}

// ---------------- masked top-8+eye via list filter (+fallback) + outlier ----------
__global__ void k_outlier(int slot){
  __shared__ unsigned long long sb[WPB*128];
  int w = threadIdx.x >> 5;
  int lane = threadIdx.x & 31;
  int row = blockIdx.x*WPB + w;
  if (row >= BN) return;
  int b = row >> 11, i = row & (N_-1);
  int mi = g_maskA[row];

  int ei = g_nn1i[row*32+lane];
  float ed = g_nn1d[row*32+lane];
  bool okm = (ei != i) && (g_maskA[b*N_+ei] != 0);
  unsigned bal = __ballot_sync(0xffffffffu, okm);
  int avail = __popc(bal);
  int total = g_cnt[slot*B_ + b] - mi;
  int needed = total < 8 ? total : 8;

  unsigned long long out[8];
  if (avail >= needed){
    unsigned rem = bal;
    #pragma unroll
    for (int s=0; s<8; s++){
      if (rem){
        int l = __ffs(rem) - 1; rem &= rem - 1;
        float dd = __shfl_sync(0xffffffffu, ed, l);
        int jj = __shfl_sync(0xffffffffu, ei, l);
        out[s] = ((unsigned long long)__float_as_uint(dd) << 32) | (unsigned)jj;
      } else out[s] = 0x7F800000FFFFFFFFull;
    }
  } else {
    warp_topk2<8,128,true,true,false>(g_xy1p, g_xy1p, g_bitsA, row, sb + w*128, out);
  }

  if (lane == 0){
    float fx = g_flow[row*2], fy = g_flow[row*2+1];
    float sx = 0.f, sy = 0.f, cnt = 0.f;
    #pragma unroll
    for (int s=0; s<8; s++){
      float d = __uint_as_float((unsigned)(out[s] >> 32));
      float vf = (d < 5e8f) ? 1.0f : 0.0f;
      int j = (d < 5e8f) ? (int)(out[s] & 0xFFFFFFFFu) : 0;
      sx = __fmaf_rn(g_flow[(b*N_+j)*2],   vf, sx);
      sy = __fmaf_rn(g_flow[(b*N_+j)*2+1], vf, sy);
      cnt = __fadd_rn(cnt, vf);
    }
    float dv = fmaxf(cnt, 1.0f);
    float mx = __fdiv_rn(sx, dv), my = __fdiv_rn(sy, dv);
    float ddx = __fsub_rn(fx, mx), ddy = __fsub_rn(fy, my);
    float dev = sqrtf(__fadd_rn(__fmaf_rn(ddy, ddy, __fmul_rn(ddx, ddx)), EPSF));
    bool keep = mi && ((cnt > 0.0f) ? (dev <= 2.0f) : true);
    g_idx1[row] = keep ? (g_idxA[row] + 1) : 0;
  }
}

__global__ void k_dedup(){
  __shared__ int cnt[N_+1];
  int b = blockIdx.x, tid = threadIdx.x;
  for (int s = tid; s < N_+1; s += 1024) cnt[s] = 0;
  __syncthreads();
  int v0 = g_idx1[b*N_ + tid], v1 = g_idx1[b*N_ + tid + 1024];
  atomicAdd(&cnt[v0], 1); atomicAdd(&cnt[v1], 1);
  __syncthreads();
  if (cnt[v0] > 1) g_idx1[b*N_ + tid] = 0;
  if (cnt[v1] > 1) g_idx1[b*N_ + tid + 1024] = 0;
}

__global__ void k_finish(const float* __restrict__ xy1, const float* __restrict__ xy2,
                         float* __restrict__ outp, int withmask, int slot){
  int row = blockIdx.x*blockDim.x + threadIdx.x;
  int b = row / N_;
  int v = g_idx1[row];
  int mm = (v != 0);
  int j = (v - 1) * mm;
  float mf = (float)mm;
  float fx = __fmul_rn(__fsub_rn(xy2[(b*N_+j)*2],   xy1[row*2]),   mf);
  float fy = __fmul_rn(__fsub_rn(xy2[(b*N_+j)*2+1], xy1[row*2+1]), mf);
  g_flow[row*2] = fx; g_flow[row*2+1] = fy;
  g_mask[row] = mm;
  if (outp){
    outp[row*2] = fx; outp[row*2+1] = fy;
    if (withmask) outp[2*BN + row] = mf;
  }
  unsigned bal = __ballot_sync(0xffffffffu, mm);
  if ((threadIdx.x & 31) == 0){
    g_bitsM[row >> 5] = bal;
    atomicAdd(&g_cnt[slot*B_ + b], __popc(bal));
  }
}

// ---------------- masked top-4 via list filter (+fallback) + IDW + xy11 prep -------
__global__ void k_griddata(int slot){
  __shared__ unsigned long long sb[WPB*128];
  int w = threadIdx.x >> 5;
  int lane = threadIdx.x & 31;
  int row = blockIdx.x*WPB + w;
  if (row >= BN) return;
  int b = row >> 11;

  int ei = g_nn1i[row*32+lane];
  float ed = g_nn1d[row*32+lane];
  bool okm = (g_mask[b*N_+ei] != 0);
  unsigned bal = __ballot_sync(0xffffffffu, okm);
  int avail = __popc(bal);
  int total = g_cnt[slot*B_ + b];
  int needed = total < 4 ? total : 4;

  unsigned long long out[4];
  if (avail >= needed){
    unsigned rem = bal;
    #pragma unroll
    for (int s=0; s<4; s++){
      if (rem){
        int l = __ffs(rem) - 1; rem &= rem - 1;
        float dd = __shfl_sync(0xffffffffu, ed, l);
        int jj = __shfl_sync(0xffffffffu, ei, l);
        out[s] = ((unsigned long long)__float_as_uint(dd) << 32) | (unsigned)jj;
      } else out[s] = 0x7F800000FFFFFFFFull;
    }
  } else {
    warp_topk2<4,128,true,false,false>(g_xy1p, g_xy1p, g_bitsM, row, sb + w*128, out);
  }

  if (lane == 0){
    float ws = 0.f, sx = 0.f, sy = 0.f;
    #pragma unroll
    for (int s=0; s<4; s++){
      float d = __uint_as_float((unsigned)(out[s] >> 32));
      float vf = (d < 5e8f) ? 1.0f : 0.0f;
      int j = (d < 5e8f) ? (int)(out[s] & 0xFFFFFFFFu) : 0;
      float wt = __fdiv_rn(vf, __fadd_rn(d, 1e-6f));
      sx = __fmaf_rn(wt, g_flow[(b*N_+j)*2],   sx);
      sy = __fmaf_rn(wt, g_flow[(b*N_+j)*2+1], sy);
      ws = __fadd_rn(ws, wt);
    }
    float ix = __fdiv_rn(sx, __fadd_rn(ws, EPSF));
    float iy = __fdiv_rn(sy, __fadd_rn(ws, EPSF));
    int m = g_mask[row];
    float gx = m ? g_flow[row*2]   : ix;
    float gy = m ? g_flow[row*2+1] : iy;
    float4 p = g_xy1p[row];
    float nx = __fadd_rn(p.x, gx);
    float ny = __fadd_rn(p.y, gy);
    g_xy11p[row] = make_float4(nx, ny, __fmaf_rn(ny, ny, __fmul_rn(nx, nx)), 0.f);
  }
}

// ---------------- dual knn_match scans: row top-2 and col top-1 (D space) ----------
__global__ void k_knn21(){
  __shared__ unsigned long long sb[WPB*128];
  int w = threadIdx.x >> 5;
  int row2 = blockIdx.x*WPB + w;
  if (row2 >= 2*BN) return;
  bool first = row2 < BN;
  int row = first ? row2 : row2 - BN;
  const float4* Q = first ? g_xy11p : g_xy2p;
  const float4* R = first ? g_xy2p  : g_xy11p;
  unsigned long long out[2];
  warp_topk2<2,128,false,false,true>(Q, R, nullptr, row, sb + w*128, out);
  if ((threadIdx.x & 31) == 0){
    if (first){
      g_rowIdx[row*2]   = (int)(out[0] & 0xFFFFFFFFu);
      g_rowIdx[row*2+1] = (int)(out[1] & 0xFFFFFFFFu);
      g_rowD[row*2]   = __uint_as_float((unsigned)(out[0] >> 32));
      g_rowD[row*2+1] = __uint_as_float((unsigned)(out[1] >> 32));
    } else {
      g_colArg[row] = (int)(out[0] & 0xFFFFFFFFu);
    }
  }
}

// ---------------- host orchestration ----------------
extern "C" void kernel_launch(void* const* d_in, const int* in_sizes, int n_in,
                              void* d_out, int out_size){
  const float* xy1 = (const float*)d_in[0];
  const float* xy2 = (const float*)d_in[1];
  const float* f1  = (const float*)d_in[2];
  const float* f2  = (const float*)d_in[3];
  const float* gam = (const float*)d_in[4];
  const float* eps = (const float*)d_in[5];
  float* outp = (float*)d_out;
  int withmask = (out_size >= BN*3) ? 1 : 0;

  static bool attr_done = false;
  if (!attr_done){
    cudaFuncSetAttribute(k_sinkhorn_all, cudaFuncAttributeMaxDynamicSharedMemorySize, 81920);
    attr_done = true;
  }

  const int WB = WPB*32;            // 256 threads
  const int GW = BN/WPB;            // 512 blocks
  const int GW2 = 2*BN/WPB;         // 1024 blocks
  const int TB = 256, GT = BN/TB;

  int slotA = 0;    // counts of maskA (outlier consumers)
  int slotM = 10;   // counts of mask (griddata consumers)

  k_init<<<(2*BN*32)/256, 256>>>(f1, f2, gam, eps);
  k_prep2<<<(2*BN)/256, 256>>>(xy1, xy2);
  k_knnpre<<<GW2, WB>>>();

  // ---- two sinkhorn matching passes ----
  for (int pass = 0; pass < 2; pass++){
    k_knn4kc<<<GW, WB>>>(pass);
    k_sinkhorn_all<<<dim3(B_,4), 1024, 81920>>>();
    for (int r = 0; r < 4; r++){
      if (r == 0) k_simmerge<8,0><<<GT, TB>>>(xy1, xy2, r, slotA);
      else        k_simmerge<8,1><<<GT, TB>>>(xy1, xy2, r, slotA);
      k_outlier<<<GW, WB>>>(slotA);
      slotA++;
      if (r > 0) k_dedup<<<2, 1024>>>();
    }
    k_finish<<<GT, TB>>>(xy1, xy2, nullptr, 0, slotM);
    k_griddata<<<GW, WB>>>(slotM);
    slotM++;
  }

  // ---- two KNN matching passes ----
  for (int pass = 0; pass < 2; pass++){
    int final = (pass == 1);
    k_knn21<<<GW2, WB>>>();
    k_simmerge<11,2><<<GT, TB>>>(xy1, xy2, 0, slotA);
    k_outlier<<<GW, WB>>>(slotA);
    slotA++;
    k_finish<<<GT, TB>>>(xy1, xy2, final ? outp : nullptr, withmask, slotM);
    if (!final){
      k_griddata<<<GW, WB>>>(slotM);
      slotM++;
    }
  }
}